// round 8
// baseline (speedup 1.0000x reference)
#include <cuda_runtime.h>
#include <cstdint>
#include <cmath>

#define ZDIM 8192
#define NOUT 448

#define K0TOT 4736          // out0 padded K (592 groups)
#define K2TOT 2304          // out2 padded K (288 groups)
#define NG0   592
#define NG2   288

// ===================== device globals (no allocation) =====================
static __device__ float g_B0t[64 * K0TOT];         // out0 weights [w][k'], prescaled + tf32
static __device__ float g_B6t[64 * K2TOT];         // out2 weights [w][k'], prescaled + tf32
static __device__ float g_B3p[4096 * 64];          // out1 weights [n=(m*64+w)][u], tf32
static __device__ float g_T[(size_t)ZDIM * 4096];  // T = s @ w3 scratch [z][m*64+w]
static __device__ unsigned short g_desc0[NG0];     // group descriptors: type<<12|u<<6|v0
static __device__ unsigned short g_desc2[NG2];

// ===================== helpers =====================
__device__ __forceinline__ uint32_t rna(float f) {
    uint32_t r; asm("cvt.rna.tf32.f32 %0, %1;" : "=r"(r) : "f"(f)); return r;
}
__device__ __forceinline__ float u2f(uint32_t u) { return __uint_as_float(u); }
__device__ __forceinline__ void mma8(float* c, const uint32_t* a, const uint32_t* b) {
    asm volatile("mma.sync.aligned.m16n8k8.row.col.f32.tf32.tf32.f32 "
        "{%0,%1,%2,%3}, {%4,%5,%6,%7}, {%8,%9}, {%0,%1,%2,%3};"
        : "+f"(c[0]), "+f"(c[1]), "+f"(c[2]), "+f"(c[3])
        : "r"(a[0]), "r"(a[1]), "r"(a[2]), "r"(a[3]), "r"(b[0]), "r"(b[1]));
}
__device__ __forceinline__ int triq(int u, int v) {   // triu index, valid v>u
    return u * 63 - (u * (u - 1)) / 2 + (v - u - 1);
}

// ===================== setup kernels =====================
// Feature group layout (8 features per group, all LDS.128-friendly):
//   out0: [ss pairs: 287 grps][s^2: 8][vdot pairs: 287][|v|^2: 8][pad: 2]  = 592
//   out2: [cross pairs: 287][pad: 1]                                      = 288
// pair groups: for u=0..62, octets j=(u>>3)..7 -> desc(type,u,v0=8j); v<=u slots get 0 weight.
__global__ void init_tables_kernel() {
    int u = threadIdx.x;  // 64 threads
    if (u < 63) {
        int B = u >> 3, r = u & 7;
        int cum = 8 * (8 * B - (B * (B - 1)) / 2) + r * (8 - B);
        int cnt = 8 - B;
        for (int t = 0; t < cnt; ++t) {
            int v0 = 8 * (B + t);
            g_desc0[cum + t]       = (unsigned short)((0 << 12) | (u << 6) | v0);  // ss
            g_desc0[295 + cum + t] = (unsigned short)((2 << 12) | (u << 6) | v0);  // vdot
            g_desc2[cum + t]       = (unsigned short)((0 << 12) | (u << 6) | v0);  // cross
        }
    }
    if (u < 8) {
        g_desc0[287 + u] = (unsigned short)((1 << 12) | (8 * u));   // s^2 octet
        g_desc0[582 + u] = (unsigned short)((3 << 12) | (8 * u));   // |v|^2 octet
    }
    if (u < 2) g_desc0[590 + u] = (unsigned short)(4 << 12);        // pad
    if (u == 0) g_desc2[287] = (unsigned short)(4 << 12);           // pad
}

__global__ void prep_w_kernel(const float* __restrict__ w1, const float* __restrict__ w2,
                              const float* __restrict__ w3, const float* __restrict__ w4,
                              const float* __restrict__ w5, const float* __restrict__ w6,
                              float c1, float c2, float c5s, float c6s) {
    int i = blockIdx.x * blockDim.x + threadIdx.x;
    const int N0 = 64 * K0TOT, N1 = 64 * K2TOT, N2 = 4096 * 64;
    if (i < N0) {
        int w = i / K0TOT, k = i - w * K0TOT;
        unsigned d = g_desc0[k >> 3];
        int ty = d >> 12, u = (d >> 6) & 63, v = (d & 63) + (k & 7);
        float val = 0.0f;
        if (ty == 0)      { if (v > u) val = c1  * w1[triq(u, v) * 64 + w]; }
        else if (ty == 1) { val = c2  * w2[v * 64 + w]; }
        else if (ty == 2) { if (v > u) val = c2  * w4[triq(u, v) * 64 + w]; }
        else if (ty == 3) { val = c5s * w5[v * 64 + w]; }
        g_B0t[i] = u2f(rna(val));
    } else if (i < N0 + N1) {
        int j = i - N0;
        int w = j / K2TOT, k = j - w * K2TOT;
        unsigned d = g_desc2[k >> 3];
        int ty = d >> 12, u = (d >> 6) & 63, v = (d & 63) + (k & 7);
        float val = 0.0f;
        if (ty == 0 && v > u) val = c6s * w6[triq(u, v) * 64 + w];
        g_B6t[j] = u2f(rna(val));
    } else if (i < N0 + N1 + N2) {
        int j = i - N0 - N1;
        int n = j >> 6, u = j & 63;                  // n = m*64+w
        g_B3p[j] = u2f(rna(w3[(size_t)u * 4096 + n]));
    }
}

// ===================== main fused kernel (templated, 512 threads) =====================
// CTA 128z x 64w, 16 warps, warp tile 32M x 16N (4M x 4N).
// MODE 0: out0; y = K-split 0..3 (37 chunks each).        atomicAdd epilogue.
// MODE 2: out2; y -> (comp = y>>1, ksplit = y&1), 36 ch.  atomicAdd epilogue.
template<int MODE>
__global__ __launch_bounds__(512) void main_kernel(const float* __restrict__ x,
                                                   float* __restrict__ out) {
    extern __shared__ __align__(16) float dsm[];
    float* As = dsm;                                 // [2][128][36] pair-interleaved (k,k+4)
    float* Bs = dsm + 2 * 128 * 36;                  // [2][64][36]  pair-interleaved (k,k+4)
    float* xs = Bs + 2 * 64 * 36;                    // [128][260]
    unsigned short* dscS = (unsigned short*)(xs + 128 * 260);

    const int tid = threadIdx.x, lane = tid & 31, wid = tid >> 5;
    const int warpM = wid & 3, warpN = wid >> 2;
    const int g = lane >> 2, q4 = lane & 3;
    const int z0 = blockIdx.x * 128;
    const int y = blockIdx.y;

    int NCH, kofs, kz = 0;
    if (MODE == 0) { NCH = 37; kofs = y * 1184; }
    else           { NCH = 36; kz = y >> 1; kofs = (y & 1) * 1152; }
    const int gbase = kofs >> 3;
    const int LDB = (MODE == 0) ? K0TOT : K2TOT;
    const float* Bsrc = (MODE == 0) ? g_B0t : g_B6t;
    const int ca = (kz + 1) % 3, cb = (kz + 2) % 3;
    const int NG = (MODE == 0) ? NG0 : NG2;

    // ---- stage x tile + descriptor table ----
    {
        int col = tid & 255, r0 = tid >> 8;
        #pragma unroll 4
        for (int j = r0; j < 128; j += 2)
            xs[j * 260 + col] = x[(size_t)(z0 + j) * 256 + col];
    }
    for (int i = tid; i < NG; i += 512)
        dscS[i] = (MODE == 0) ? g_desc0[i] : g_desc2[i];

    const int row = tid >> 2, h = tid & 3;           // 128 rows x 4 groups/chunk
    const float* xr = xs + row * 260;
    const int brow = tid >> 3, bc4 = tid & 7;        // B stage: 64 rows x 8 float4
    const float* bbase = Bsrc + (size_t)brow * LDB + kofs + bc4 * 4;
    const int bk8 = bc4 >> 1, bk4 = bc4 & 1;         // interleave targets

    float acc[2][2][4];
    #pragma unroll
    for (int mt = 0; mt < 2; ++mt)
        #pragma unroll
        for (int nt = 0; nt < 2; ++nt)
            #pragma unroll
            for (int j = 0; j < 4; ++j) acc[mt][nt][j] = 0.0f;

    uint32_t fr[8];
    float4 rb;

    // ---- feature generation: one 8-feature group per thread (descriptor-driven) ----
    #define GEN(CC) do {                                                          \
        unsigned d = dscS[gbase + (CC) * 4 + h];                                  \
        int ty = d >> 12, uu = (d >> 6) & 63, v0 = d & 63;                        \
        float f[8];                                                               \
        if (MODE == 0 && ty <= 1) {                                               \
            float4 p  = *(const float4*)(xr + v0);                                \
            float4 p2 = *(const float4*)(xr + v0 + 4);                            \
            float su = (ty == 0) ? xr[uu] : 0.0f;                                 \
            if (ty == 0) {                                                        \
                f[0]=su*p.x; f[1]=su*p.y; f[2]=su*p.z; f[3]=su*p.w;               \
                f[4]=su*p2.x; f[5]=su*p2.y; f[6]=su*p2.z; f[7]=su*p2.w;           \
            } else {                                                              \
                f[0]=p.x*p.x; f[1]=p.y*p.y; f[2]=p.z*p.z; f[3]=p.w*p.w;           \
                f[4]=p2.x*p2.x; f[5]=p2.y*p2.y; f[6]=p2.z*p2.z; f[7]=p2.w*p2.w;   \
            }                                                                     \
        } else if ((MODE == 0 && ty <= 3) || (MODE == 2 && ty == 0)) {            \
            const float* wv = xr + 64 + 3 * v0;                                   \
            float Bv[24];                                                         \
            _Pragma("unroll")                                                     \
            for (int t6 = 0; t6 < 6; ++t6) {                                      \
                float4 bb = *(const float4*)(wv + 4 * t6);                        \
                Bv[4*t6]=bb.x; Bv[4*t6+1]=bb.y; Bv[4*t6+2]=bb.z; Bv[4*t6+3]=bb.w; \
            }                                                                     \
            if (MODE == 2) {                                                      \
                float a0 = xr[64 + 3*uu + ca], a1 = xr[64 + 3*uu + cb];           \
                _Pragma("unroll")                                                 \
                for (int i = 0; i < 8; ++i)                                       \
                    f[i] = a0 * Bv[3*i + cb] - a1 * Bv[3*i + ca];                 \
            } else if (ty == 2) {                                                 \
                float a0 = xr[64+3*uu], a1 = xr[64+3*uu+1], a2 = xr[64+3*uu+2];   \
                _Pragma("unroll")                                                 \
                for (int i = 0; i < 8; ++i)                                       \
                    f[i] = a0*Bv[3*i] + a1*Bv[3*i+1] + a2*Bv[3*i+2];              \
            } else {                                                              \
                _Pragma("unroll")                                                 \
                for (int i = 0; i < 8; ++i)                                       \
                    f[i] = Bv[3*i]*Bv[3*i] + Bv[3*i+1]*Bv[3*i+1]                  \
                         + Bv[3*i+2]*Bv[3*i+2];                                   \
            }                                                                     \
        } else {                                                                  \
            _Pragma("unroll")                                                     \
            for (int i = 0; i < 8; ++i) f[i] = 0.0f;                              \
        }                                                                         \
        _Pragma("unroll")                                                         \
        for (int i = 0; i < 8; ++i) fr[i] = rna(f[i]);                            \
    } while (0)

    #define STORE_A(CC) do {                                                      \
        float* ap = As + ((CC) & 1) * (128 * 36) + row * 36 + h * 8;              \
        _Pragma("unroll")                                                         \
        for (int j = 0; j < 4; ++j)                                               \
            *(float2*)(ap + j * 2) = make_float2(u2f(fr[j]), u2f(fr[j + 4]));     \
    } while (0)

    #define STORE_B(CC) do {                                                      \
        float* bp = Bs + ((CC) & 1) * (64 * 36) + brow * 36 + bk8 * 8 + bk4;      \
        bp[0] = rb.x; bp[2] = rb.y; bp[4] = rb.z; bp[6] = rb.w;                   \
    } while (0)

    // prologue: chunk 0
    __syncthreads();
    rb = *(const float4*)(bbase);
    GEN(0);
    STORE_A(0);
    STORE_B(0);
    __syncthreads();

    for (int c = 0; c < NCH; ++c) {
        bool more = (c + 1 < NCH);
        if (more) {
            rb = *(const float4*)(bbase + (c + 1) * 32);
            GEN(c + 1);
            STORE_A(c + 1);
        }
        {
            const float* Ab = As + (c & 1) * (128 * 36) + (warpM * 32) * 36;
            const float* Bb = Bs + (c & 1) * (64 * 36) + (warpN * 16) * 36;
            #pragma unroll
            for (int k8 = 0; k8 < 4; ++k8) {
                uint32_t a[2][4], b[2][2];
                #pragma unroll
                for (int mt = 0; mt < 2; ++mt) {
                    float2 lo = *(const float2*)(Ab + (mt * 16 + g) * 36 + k8 * 8 + q4 * 2);
                    float2 hi = *(const float2*)(Ab + (mt * 16 + 8 + g) * 36 + k8 * 8 + q4 * 2);
                    a[mt][0] = __float_as_uint(lo.x); a[mt][1] = __float_as_uint(hi.x);
                    a[mt][2] = __float_as_uint(lo.y); a[mt][3] = __float_as_uint(hi.y);
                }
                #pragma unroll
                for (int nt = 0; nt < 2; ++nt) {
                    float2 bv = *(const float2*)(Bb + (nt * 8 + g) * 36 + k8 * 8 + q4 * 2);
                    b[nt][0] = __float_as_uint(bv.x); b[nt][1] = __float_as_uint(bv.y);
                }
                #pragma unroll
                for (int mt = 0; mt < 2; ++mt)
                    #pragma unroll
                    for (int nt = 0; nt < 2; ++nt)
                        mma8(acc[mt][nt], a[mt], b[nt]);
            }
        }
        if (more) STORE_B(c + 1);
        __syncthreads();
    }

    // ---- epilogue (both modes: split-K -> atomicAdd into zeroed out) ----
    #pragma unroll
    for (int mt = 0; mt < 2; ++mt) {
        int za = z0 + warpM * 32 + mt * 16 + g;
        int zb = za + 8;
        #pragma unroll
        for (int nt = 0; nt < 2; ++nt) {
            int col = warpN * 16 + nt * 8 + q4 * 2;
            if (MODE == 0) {
                atomicAdd(out + (size_t)za * NOUT + col,     acc[mt][nt][0]);
                atomicAdd(out + (size_t)za * NOUT + col + 1, acc[mt][nt][1]);
                atomicAdd(out + (size_t)zb * NOUT + col,     acc[mt][nt][2]);
                atomicAdd(out + (size_t)zb * NOUT + col + 1, acc[mt][nt][3]);
            } else {
                atomicAdd(out + (size_t)za * NOUT + 256 + col * 3 + kz,       acc[mt][nt][0]);
                atomicAdd(out + (size_t)za * NOUT + 256 + (col + 1) * 3 + kz, acc[mt][nt][1]);
                atomicAdd(out + (size_t)zb * NOUT + 256 + col * 3 + kz,       acc[mt][nt][2]);
                atomicAdd(out + (size_t)zb * NOUT + 256 + (col + 1) * 3 + kz, acc[mt][nt][3]);
            }
        }
    }
    #undef GEN
    #undef STORE_A
    #undef STORE_B
}

// ===================== out1 pass A: T = rna(s) @ B3p^T   (M=8192, N=4096, K=64) ==========
__global__ __launch_bounds__(256) void tgemm_kernel(const float* __restrict__ x) {
    extern __shared__ __align__(16) float dsm[];
    float* As = dsm;             // [128][72]
    float* Bs = dsm + 128 * 72;  // [128][72]

    const int tid = threadIdx.x, lane = tid & 31, wid = tid >> 5;
    const int warpM = wid & 3, warpN = wid >> 2;
    const int g = lane >> 2, q4 = lane & 3;
    const int z0 = blockIdx.x * 128, n0 = blockIdx.y * 128;
    const int r = tid >> 1, h = tid & 1;

    {
        const float* src = x + (size_t)(z0 + r) * 256 + h * 32;
        float* dst = As + r * 72 + h * 36;
        #pragma unroll
        for (int je = 0; je < 8; je += 2) {
            float4 v0 = *(const float4*)(src + je * 4);
            float4 v1 = *(const float4*)(src + je * 4 + 4);
            *(float2*)(dst + je * 4 + 0) = make_float2(u2f(rna(v0.x)), u2f(rna(v1.x)));
            *(float2*)(dst + je * 4 + 2) = make_float2(u2f(rna(v0.y)), u2f(rna(v1.y)));
            *(float2*)(dst + je * 4 + 4) = make_float2(u2f(rna(v0.z)), u2f(rna(v1.z)));
            *(float2*)(dst + je * 4 + 6) = make_float2(u2f(rna(v0.w)), u2f(rna(v1.w)));
        }
    }
    {
        const float* src = g_B3p + (size_t)(n0 + r) * 64 + h * 32;
        float* dst = Bs + r * 72 + h * 36;
        #pragma unroll
        for (int je = 0; je < 8; je += 2) {
            float4 v0 = *(const float4*)(src + je * 4);
            float4 v1 = *(const float4*)(src + je * 4 + 4);
            *(float2*)(dst + je * 4 + 0) = make_float2(v0.x, v1.x);
            *(float2*)(dst + je * 4 + 2) = make_float2(v0.y, v1.y);
            *(float2*)(dst + je * 4 + 4) = make_float2(v0.z, v1.z);
            *(float2*)(dst + je * 4 + 6) = make_float2(v0.w, v1.w);
        }
    }
    __syncthreads();

    float acc[2][8][4];
    #pragma unroll
    for (int mt = 0; mt < 2; ++mt)
        #pragma unroll
        for (int nt = 0; nt < 8; ++nt)
            #pragma unroll
            for (int j = 0; j < 4; ++j) acc[mt][nt][j] = 0.0f;

    #pragma unroll
    for (int ch = 0; ch < 2; ++ch) {
        #pragma unroll
        for (int k8 = 0; k8 < 4; ++k8) {
            int ko = ch * 36 + k8 * 8 + q4 * 2;
            uint32_t a[2][4], b[8][2];
            #pragma unroll
            for (int mt = 0; mt < 2; ++mt) {
                float2 lo = *(const float2*)(As + (warpM * 32 + mt * 16 + g) * 72 + ko);
                float2 hi = *(const float2*)(As + (warpM * 32 + mt * 16 + 8 + g) * 72 + ko);
                a[mt][0] = __float_as_uint(lo.x); a[mt][1] = __float_as_uint(hi.x);
                a[mt][2] = __float_as_uint(lo.y); a[mt][3] = __float_as_uint(hi.y);
            }
            #pragma unroll
            for (int nt = 0; nt < 8; ++nt) {
                float2 bv = *(const float2*)(Bs + (warpN * 64 + nt * 8 + g) * 72 + ko);
                b[nt][0] = __float_as_uint(bv.x); b[nt][1] = __float_as_uint(bv.y);
            }
            #pragma unroll
            for (int mt = 0; mt < 2; ++mt)
                #pragma unroll
                for (int nt = 0; nt < 8; ++nt)
                    mma8(acc[mt][nt], a[mt], b[nt]);
        }
    }

    #pragma unroll
    for (int mt = 0; mt < 2; ++mt) {
        int za = z0 + warpM * 32 + mt * 16 + g;
        #pragma unroll
        for (int nt = 0; nt < 8; ++nt) {
            int n = n0 + warpN * 64 + nt * 8 + q4 * 2;
            *(float2*)(g_T + (size_t)za * 4096 + n)       = make_float2(acc[mt][nt][0], acc[mt][nt][1]);
            *(float2*)(g_T + (size_t)(za + 8) * 4096 + n) = make_float2(acc[mt][nt][2], acc[mt][nt][3]);
        }
    }
}

// ===================== out1 pass B: out1[z,w,k] = (1/64) * sum_m T[z,m*64+w] * v[z,m,k] ====
__global__ __launch_bounds__(256) void contract_kernel(const float* __restrict__ x,
                                                       float* __restrict__ out) {
    int tid = threadIdx.x;
    int wp = tid >> 5, lane = tid & 31;
    size_t z = (size_t)blockIdx.x * 8 + wp;
    const float* Trow = g_T + z * 4096;
    const float* vp = x + z * 256 + 64;
    float a00 = 0.f, a01 = 0.f, a02 = 0.f, a10 = 0.f, a11 = 0.f, a12 = 0.f;
    #pragma unroll 4
    for (int m = 0; m < 64; ++m) {
        float t0 = Trow[m * 64 + lane];
        float t1 = Trow[m * 64 + 32 + lane];
        float vx = vp[m * 3 + 0], vy = vp[m * 3 + 1], vz = vp[m * 3 + 2];
        a00 += t0 * vx; a01 += t0 * vy; a02 += t0 * vz;
        a10 += t1 * vx; a11 += t1 * vy; a12 += t1 * vz;
    }
    float* base = out + z * NOUT + 64;
    const float sc = 0.015625f;
    base[lane * 3 + 0] = a00 * sc; base[lane * 3 + 1] = a01 * sc; base[lane * 3 + 2] = a02 * sc;
    base[(lane + 32) * 3 + 0] = a10 * sc; base[(lane + 32) * 3 + 1] = a11 * sc; base[(lane + 32) * 3 + 2] = a12 * sc;
}

// ===================== launch =====================
extern "C" void kernel_launch(void* const* d_in, const int* in_sizes, int n_in,
                              void* d_out, int out_size) {
    const float* x  = (const float*)d_in[0];
    const float* w1 = (const float*)d_in[1];
    const float* w2 = (const float*)d_in[2];
    const float* w3 = (const float*)d_in[3];
    const float* w4 = (const float*)d_in[4];
    const float* w5 = (const float*)d_in[5];
    const float* w6 = (const float*)d_in[6];
    float* out = (float*)d_out;

    float c1  = (float)sqrt(1.0 / 4160.0);     // C1
    float c2  = (float)sqrt(1.0 / 12480.0);    // C2 == C4/sqrt(3)
    float c5s = (float)sqrt(1.0 / 62400.0);    // C5/sqrt(3)
    float c6s = (float)sqrt(1.0 / 4032.0);     // C6/sqrt(6)

    const int MAIN_SMEM = (2 * 128 * 36 + 2 * 64 * 36 + 128 * 260) * 4 + NG0 * 2;  // 189,600
    const int TG_SMEM   = 2 * 128 * 72 * 4;                                         //  73,728
    cudaFuncSetAttribute(main_kernel<0>, cudaFuncAttributeMaxDynamicSharedMemorySize, MAIN_SMEM);
    cudaFuncSetAttribute(main_kernel<2>, cudaFuncAttributeMaxDynamicSharedMemorySize, MAIN_SMEM);
    cudaFuncSetAttribute(tgemm_kernel,   cudaFuncAttributeMaxDynamicSharedMemorySize, TG_SMEM);

    cudaMemsetAsync(d_out, 0, (size_t)out_size * sizeof(float));
    init_tables_kernel<<<1, 64>>>();
    const int NTOT = 64 * K0TOT + 64 * K2TOT + 4096 * 64;
    prep_w_kernel<<<(NTOT + 255) / 256, 256>>>(w1, w2, w3, w4, w5, w6, c1, c2, c5s, c6s);

    main_kernel<2><<<dim3(64, 6), 512, MAIN_SMEM>>>(x, out);  // out2: 3 comps x 2 K-splits
    main_kernel<0><<<dim3(64, 4), 512, MAIN_SMEM>>>(x, out);  // out0: 4 K-splits
    tgemm_kernel<<<dim3(64, 32), 256, TG_SMEM>>>(x);          // T = s @ w3
    contract_kernel<<<ZDIM / 8, 256>>>(x, out);               // out1
}

// round 9
// speedup vs baseline: 1.2832x; 1.2832x over previous
#include <cuda_runtime.h>
#include <cstdint>
#include <cmath>

#define ZDIM 8192
#define NOUT 448

#define K0TOT 4736          // out0 padded K (592 groups)
#define K2TOT 2304          // out2 padded K (288 groups)
#define NG0   592
#define NG2   288

// ===================== device globals (no allocation) =====================
static __device__ float g_B0t[64 * K0TOT];         // out0 weights [w][k'], prescaled + tf32
static __device__ float g_B6t[64 * K2TOT];         // out2 weights [w][k'], prescaled + tf32
static __device__ float g_B3p[4096 * 64];          // out1 weights [n=(w*64+m)][u], tf32
static __device__ unsigned short g_desc0[NG0];     // group descriptors: type<<12|u<<6|v0
static __device__ unsigned short g_desc2[NG2];

// ===================== helpers =====================
__device__ __forceinline__ uint32_t rna(float f) {
    uint32_t r; asm("cvt.rna.tf32.f32 %0, %1;" : "=r"(r) : "f"(f)); return r;
}
__device__ __forceinline__ float u2f(uint32_t u) { return __uint_as_float(u); }
__device__ __forceinline__ void mma8(float* c, const uint32_t* a, const uint32_t* b) {
    asm volatile("mma.sync.aligned.m16n8k8.row.col.f32.tf32.tf32.f32 "
        "{%0,%1,%2,%3}, {%4,%5,%6,%7}, {%8,%9}, {%0,%1,%2,%3};"
        : "+f"(c[0]), "+f"(c[1]), "+f"(c[2]), "+f"(c[3])
        : "r"(a[0]), "r"(a[1]), "r"(a[2]), "r"(a[3]), "r"(b[0]), "r"(b[1]));
}
__device__ __forceinline__ int triq(int u, int v) {   // triu index, valid v>u
    return u * 63 - (u * (u - 1)) / 2 + (v - u - 1);
}

// ===================== setup kernels =====================
__global__ void init_tables_kernel() {
    int u = threadIdx.x;  // 64 threads
    if (u < 63) {
        int B = u >> 3, r = u & 7;
        int cum = 8 * (8 * B - (B * (B - 1)) / 2) + r * (8 - B);
        int cnt = 8 - B;
        for (int t = 0; t < cnt; ++t) {
            int v0 = 8 * (B + t);
            g_desc0[cum + t]       = (unsigned short)((0 << 12) | (u << 6) | v0);  // ss
            g_desc0[295 + cum + t] = (unsigned short)((2 << 12) | (u << 6) | v0);  // vdot
            g_desc2[cum + t]       = (unsigned short)((0 << 12) | (u << 6) | v0);  // cross
        }
    }
    if (u < 8) {
        g_desc0[287 + u] = (unsigned short)((1 << 12) | (8 * u));   // s^2 octet
        g_desc0[582 + u] = (unsigned short)((3 << 12) | (8 * u));   // |v|^2 octet
    }
    if (u < 2) g_desc0[590 + u] = (unsigned short)(4 << 12);        // pad
    if (u == 0) g_desc2[287] = (unsigned short)(4 << 12);           // pad
}

__global__ void prep_w_kernel(const float* __restrict__ w1, const float* __restrict__ w2,
                              const float* __restrict__ w3, const float* __restrict__ w4,
                              const float* __restrict__ w5, const float* __restrict__ w6,
                              float c1, float c2, float c5s, float c6s) {
    int i = blockIdx.x * blockDim.x + threadIdx.x;
    const int N0 = 64 * K0TOT, N1 = 64 * K2TOT, N2 = 4096 * 64;
    if (i < N0) {
        int w = i / K0TOT, k = i - w * K0TOT;
        unsigned d = g_desc0[k >> 3];
        int ty = d >> 12, u = (d >> 6) & 63, v = (d & 63) + (k & 7);
        float val = 0.0f;
        if (ty == 0)      { if (v > u) val = c1  * w1[triq(u, v) * 64 + w]; }
        else if (ty == 1) { val = c2  * w2[v * 64 + w]; }
        else if (ty == 2) { if (v > u) val = c2  * w4[triq(u, v) * 64 + w]; }
        else if (ty == 3) { val = c5s * w5[v * 64 + w]; }
        g_B0t[i] = u2f(rna(val));
    } else if (i < N0 + N1) {
        int j = i - N0;
        int w = j / K2TOT, k = j - w * K2TOT;
        unsigned d = g_desc2[k >> 3];
        int ty = d >> 12, u = (d >> 6) & 63, v = (d & 63) + (k & 7);
        float val = 0.0f;
        if (ty == 0 && v > u) val = c6s * w6[triq(u, v) * 64 + w];
        g_B6t[j] = u2f(rna(val));
    } else if (i < N0 + N1 + N2) {
        int j = i - N0 - N1;
        int n = j >> 6, u = j & 63;                  // n = w*64 + m
        int w = n >> 6, m = n & 63;
        g_B3p[j] = u2f(rna(w3[(size_t)u * 4096 + m * 64 + w]));
    }
}

// ===================== main fused kernel (templated, 512 threads) =====================
// CTA 128z x 64w, 16 warps, warp tile 32M x 16N (4M x 4N). Fragment stride 40 (conflict-free).
// x staged SoA: S / VX / VY / VZ planes, stride 68.
// MODE 0: out0; y = K-split 0..3 (37 chunks). MODE 2: out2; y = comp*2 + ksplit (36 chunks).
template<int MODE>
__global__ __launch_bounds__(512) void main_kernel(const float* __restrict__ x,
                                                   float* __restrict__ out) {
    // smem float offsets
    const int AS_OFF = 0;                 // [2][128][40]
    const int BS_OFF = 10240;             // [2][64][40]
    const int S_OFF  = 15360;             // [128][68]
    const int VX_OFF = 24064;
    const int VY_OFF = 32768;
    const int VZ_OFF = 41472;
    const int DSC_OFF = 50176;
    extern __shared__ __align__(16) float dsm[];
    unsigned short* dsc = (unsigned short*)(dsm + DSC_OFF);

    const int tid = threadIdx.x, lane = tid & 31, wid = tid >> 5;
    const int warpM = wid & 3, warpN = wid >> 2;
    const int g = lane >> 2, q4 = lane & 3;
    const int z0 = blockIdx.x * 128;
    const int y = blockIdx.y;

    int NCH, kofs, kz = 0;
    if (MODE == 0) { NCH = 37; kofs = y * 1184; }
    else           { NCH = 36; kz = y >> 1; kofs = (y & 1) * 1152; }
    const int gbase = kofs >> 3;
    const int LDB = (MODE == 0) ? K0TOT : K2TOT;
    const float* Bsrc = (MODE == 0) ? g_B0t : g_B6t;
    const int ca = (kz + 1) % 3, cb = (kz + 2) % 3;
    const int NG = (MODE == 0) ? NG0 : NG2;

    // ---- stage x tile into SoA planes + descriptor table ----
    {
        int col = tid & 255, r0 = tid >> 8;
        int c = col - 64;
        int m = (c >= 0) ? (c / 3) : 0;
        int k3 = c - m * 3;
        int dstoff;
        if (col < 64)       dstoff = S_OFF + col;
        else if (k3 == 0)   dstoff = VX_OFF + m;
        else if (k3 == 1)   dstoff = VY_OFF + m;
        else                dstoff = VZ_OFF + m;
        #pragma unroll 4
        for (int j = r0; j < 128; j += 2)
            dsm[dstoff + j * 68] = x[(size_t)(z0 + j) * 256 + col];
    }
    for (int i = tid; i < NG; i += 512)
        dsc[i] = (MODE == 0) ? g_desc0[i] : g_desc2[i];

    const int row = tid >> 2, h = tid & 3;           // 128 rows x 4 groups/chunk
    const float* Sp  = dsm + S_OFF  + row * 68;
    const float* pvx = dsm + VX_OFF + row * 68;
    const float* pvy = dsm + VY_OFF + row * 68;
    const float* pvz = dsm + VZ_OFF + row * 68;
    const float* Pca = dsm + ((ca == 0) ? VX_OFF : (ca == 1) ? VY_OFF : VZ_OFF) + row * 68;
    const float* Pcb = dsm + ((cb == 0) ? VX_OFF : (cb == 1) ? VY_OFF : VZ_OFF) + row * 68;
    const int brow = tid >> 3, bc4 = tid & 7;        // B stage: 64 rows x 8 float4
    const float* bbase = Bsrc + (size_t)brow * LDB + kofs + bc4 * 4;
    const int bk8 = bc4 >> 1, bk4 = bc4 & 1;

    float acc[2][2][4];
    #pragma unroll
    for (int mt = 0; mt < 2; ++mt)
        #pragma unroll
        for (int nt = 0; nt < 2; ++nt)
            #pragma unroll
            for (int j = 0; j < 4; ++j) acc[mt][nt][j] = 0.0f;

    uint32_t fr[8];
    float4 rb;

    #define GEN(CC) do {                                                          \
        unsigned d = dsc[gbase + (CC) * 4 + h];                                   \
        int ty = d >> 12, uu = (d >> 6) & 63, v0 = d & 63;                        \
        float f[8];                                                               \
        if (MODE == 0 && ty <= 1) {                                               \
            float4 p  = *(const float4*)(Sp + v0);                                \
            float4 p2 = *(const float4*)(Sp + v0 + 4);                            \
            if (ty == 0) {                                                        \
                float su = Sp[uu];                                                \
                f[0]=su*p.x;  f[1]=su*p.y;  f[2]=su*p.z;  f[3]=su*p.w;            \
                f[4]=su*p2.x; f[5]=su*p2.y; f[6]=su*p2.z; f[7]=su*p2.w;           \
            } else {                                                              \
                f[0]=p.x*p.x;   f[1]=p.y*p.y;   f[2]=p.z*p.z;   f[3]=p.w*p.w;     \
                f[4]=p2.x*p2.x; f[5]=p2.y*p2.y; f[6]=p2.z*p2.z; f[7]=p2.w*p2.w;   \
            }                                                                     \
        } else if (MODE == 0 && ty <= 3) {                                        \
            float4 xa = *(const float4*)(pvx + v0), xb = *(const float4*)(pvx + v0 + 4); \
            float4 ya = *(const float4*)(pvy + v0), yb = *(const float4*)(pvy + v0 + 4); \
            float4 za = *(const float4*)(pvz + v0), zb = *(const float4*)(pvz + v0 + 4); \
            if (ty == 2) {                                                        \
                float ax = pvx[uu], ay = pvy[uu], az = pvz[uu];                   \
                f[0]=ax*xa.x+ay*ya.x+az*za.x; f[1]=ax*xa.y+ay*ya.y+az*za.y;       \
                f[2]=ax*xa.z+ay*ya.z+az*za.z; f[3]=ax*xa.w+ay*ya.w+az*za.w;       \
                f[4]=ax*xb.x+ay*yb.x+az*zb.x; f[5]=ax*xb.y+ay*yb.y+az*zb.y;       \
                f[6]=ax*xb.z+ay*yb.z+az*zb.z; f[7]=ax*xb.w+ay*yb.w+az*zb.w;       \
            } else {                                                              \
                f[0]=xa.x*xa.x+ya.x*ya.x+za.x*za.x; f[1]=xa.y*xa.y+ya.y*ya.y+za.y*za.y; \
                f[2]=xa.z*xa.z+ya.z*ya.z+za.z*za.z; f[3]=xa.w*xa.w+ya.w*ya.w+za.w*za.w; \
                f[4]=xb.x*xb.x+yb.x*yb.x+zb.x*zb.x; f[5]=xb.y*xb.y+yb.y*yb.y+zb.y*zb.y; \
                f[6]=xb.z*xb.z+yb.z*yb.z+zb.z*zb.z; f[7]=xb.w*xb.w+yb.w*yb.w+zb.w*zb.w; \
            }                                                                     \
        } else if (MODE == 2 && ty == 0) {                                        \
            float4 A0 = *(const float4*)(Pca + v0), A1 = *(const float4*)(Pca + v0 + 4); \
            float4 B0 = *(const float4*)(Pcb + v0), B1 = *(const float4*)(Pcb + v0 + 4); \
            float a0 = Pca[uu], a1 = Pcb[uu];                                     \
            f[0]=a0*B0.x-a1*A0.x; f[1]=a0*B0.y-a1*A0.y;                           \
            f[2]=a0*B0.z-a1*A0.z; f[3]=a0*B0.w-a1*A0.w;                           \
            f[4]=a0*B1.x-a1*A1.x; f[5]=a0*B1.y-a1*A1.y;                           \
            f[6]=a0*B1.z-a1*A1.z; f[7]=a0*B1.w-a1*A1.w;                           \
        } else {                                                                  \
            _Pragma("unroll")                                                     \
            for (int i = 0; i < 8; ++i) f[i] = 0.0f;                              \
        }                                                                         \
        _Pragma("unroll")                                                         \
        for (int i = 0; i < 8; ++i) fr[i] = rna(f[i]);                            \
    } while (0)

    #define STORE_A(CC) do {                                                      \
        float* ap = dsm + AS_OFF + ((CC) & 1) * (128 * 40) + row * 40 + h * 8;    \
        *(float4*)(ap)     = make_float4(u2f(fr[0]), u2f(fr[4]), u2f(fr[1]), u2f(fr[5])); \
        *(float4*)(ap + 4) = make_float4(u2f(fr[2]), u2f(fr[6]), u2f(fr[3]), u2f(fr[7])); \
    } while (0)

    #define STORE_B(CC) do {                                                      \
        float* bp = dsm + BS_OFF + ((CC) & 1) * (64 * 40) + brow * 40 + bk8 * 8 + bk4; \
        bp[0] = rb.x; bp[2] = rb.y; bp[4] = rb.z; bp[6] = rb.w;                   \
    } while (0)

    // prologue: chunk 0
    __syncthreads();
    rb = *(const float4*)(bbase);
    GEN(0);
    STORE_A(0);
    STORE_B(0);
    __syncthreads();

    for (int c = 0; c < NCH; ++c) {
        bool more = (c + 1 < NCH);
        if (more) {
            rb = *(const float4*)(bbase + (c + 1) * 32);
            GEN(c + 1);
            STORE_A(c + 1);
        }
        {
            const float* Ab = dsm + AS_OFF + (c & 1) * (128 * 40) + (warpM * 32) * 40;
            const float* Bb = dsm + BS_OFF + (c & 1) * (64 * 40) + (warpN * 16) * 40;
            #pragma unroll
            for (int k8 = 0; k8 < 4; ++k8) {
                uint32_t a[2][4], b[2][2];
                #pragma unroll
                for (int mt = 0; mt < 2; ++mt) {
                    float2 lo = *(const float2*)(Ab + (mt * 16 + g) * 40 + k8 * 8 + q4 * 2);
                    float2 hi = *(const float2*)(Ab + (mt * 16 + 8 + g) * 40 + k8 * 8 + q4 * 2);
                    a[mt][0] = __float_as_uint(lo.x); a[mt][1] = __float_as_uint(hi.x);
                    a[mt][2] = __float_as_uint(lo.y); a[mt][3] = __float_as_uint(hi.y);
                }
                #pragma unroll
                for (int nt = 0; nt < 2; ++nt) {
                    float2 bv = *(const float2*)(Bb + (nt * 8 + g) * 40 + k8 * 8 + q4 * 2);
                    b[nt][0] = __float_as_uint(bv.x); b[nt][1] = __float_as_uint(bv.y);
                }
                #pragma unroll
                for (int mt = 0; mt < 2; ++mt)
                    #pragma unroll
                    for (int nt = 0; nt < 2; ++nt)
                        mma8(acc[mt][nt], a[mt], b[nt]);
            }
        }
        if (more) STORE_B(c + 1);
        __syncthreads();
    }

    // ---- epilogue: split-K -> atomicAdd into zeroed out ----
    #pragma unroll
    for (int mt = 0; mt < 2; ++mt) {
        int za = z0 + warpM * 32 + mt * 16 + g;
        int zb = za + 8;
        #pragma unroll
        for (int nt = 0; nt < 2; ++nt) {
            int col = warpN * 16 + nt * 8 + q4 * 2;
            if (MODE == 0) {
                atomicAdd(out + (size_t)za * NOUT + col,     acc[mt][nt][0]);
                atomicAdd(out + (size_t)za * NOUT + col + 1, acc[mt][nt][1]);
                atomicAdd(out + (size_t)zb * NOUT + col,     acc[mt][nt][2]);
                atomicAdd(out + (size_t)zb * NOUT + col + 1, acc[mt][nt][3]);
            } else {
                atomicAdd(out + (size_t)za * NOUT + 256 + col * 3 + kz,       acc[mt][nt][0]);
                atomicAdd(out + (size_t)za * NOUT + 256 + (col + 1) * 3 + kz, acc[mt][nt][1]);
                atomicAdd(out + (size_t)zb * NOUT + 256 + col * 3 + kz,       acc[mt][nt][2]);
                atomicAdd(out + (size_t)zb * NOUT + 256 + (col + 1) * 3 + kz, acc[mt][nt][3]);
            }
        }
    }
    #undef GEN
    #undef STORE_A
    #undef STORE_B
}

// ===================== out1 fused: D = rna(s) @ B3p^T then in-epilogue v contraction ========
// CTA 128z x 128n (n = w*64+m, 2 w's per CTA). out1[z,w,k] = (1/64) * sum_m D[z,w*64+m]*v[z,m,k].
__global__ __launch_bounds__(256) void tgemm_kernel(const float* __restrict__ x,
                                                    float* __restrict__ out) {
    extern __shared__ __align__(16) float dsm[];
    float* As = dsm;                   // [128][72]
    float* Bs = dsm + 128 * 72;        // [128][72]
    float* Vs = dsm + 2 * 128 * 72;    // [128][194]  (v data for epilogue)

    const int tid = threadIdx.x, lane = tid & 31, wid = tid >> 5;
    const int warpM = wid & 3, warpN = wid >> 2;
    const int g = lane >> 2, q4 = lane & 3;
    const int z0 = blockIdx.x * 128, n0 = blockIdx.y * 128;
    const int r = tid >> 1, h = tid & 1;

    {   // stage A (rna(s)) pair-interleaved
        const float* src = x + (size_t)(z0 + r) * 256 + h * 32;
        float* dst = As + r * 72 + h * 36;
        #pragma unroll
        for (int je = 0; je < 8; je += 2) {
            float4 v0 = *(const float4*)(src + je * 4);
            float4 v1 = *(const float4*)(src + je * 4 + 4);
            *(float2*)(dst + je * 4 + 0) = make_float2(u2f(rna(v0.x)), u2f(rna(v1.x)));
            *(float2*)(dst + je * 4 + 2) = make_float2(u2f(rna(v0.y)), u2f(rna(v1.y)));
            *(float2*)(dst + je * 4 + 4) = make_float2(u2f(rna(v0.z)), u2f(rna(v1.z)));
            *(float2*)(dst + je * 4 + 6) = make_float2(u2f(rna(v0.w)), u2f(rna(v1.w)));
        }
    }
    {   // stage B (already tf32)
        const float* src = g_B3p + (size_t)(n0 + r) * 64 + h * 32;
        float* dst = Bs + r * 72 + h * 36;
        #pragma unroll
        for (int je = 0; je < 8; je += 2) {
            float4 v0 = *(const float4*)(src + je * 4);
            float4 v1 = *(const float4*)(src + je * 4 + 4);
            *(float2*)(dst + je * 4 + 0) = make_float2(v0.x, v1.x);
            *(float2*)(dst + je * 4 + 2) = make_float2(v0.y, v1.y);
            *(float2*)(dst + je * 4 + 4) = make_float2(v0.z, v1.z);
            *(float2*)(dst + je * 4 + 6) = make_float2(v0.w, v1.w);
        }
    }
    // stage v for epilogue
    for (int idx = tid; idx < 128 * 192; idx += 256) {
        int rr = idx / 192, cc = idx - rr * 192;
        Vs[rr * 194 + cc] = x[(size_t)(z0 + rr) * 256 + 64 + cc];
    }
    __syncthreads();

    float acc[2][8][4];
    #pragma unroll
    for (int mt = 0; mt < 2; ++mt)
        #pragma unroll
        for (int nt = 0; nt < 8; ++nt)
            #pragma unroll
            for (int j = 0; j < 4; ++j) acc[mt][nt][j] = 0.0f;

    #pragma unroll
    for (int ch = 0; ch < 2; ++ch) {
        #pragma unroll
        for (int k8 = 0; k8 < 4; ++k8) {
            int ko = ch * 36 + k8 * 8 + q4 * 2;
            uint32_t a[2][4], b[8][2];
            #pragma unroll
            for (int mt = 0; mt < 2; ++mt) {
                float2 lo = *(const float2*)(As + (warpM * 32 + mt * 16 + g) * 72 + ko);
                float2 hi = *(const float2*)(As + (warpM * 32 + mt * 16 + 8 + g) * 72 + ko);
                a[mt][0] = __float_as_uint(lo.x); a[mt][1] = __float_as_uint(hi.x);
                a[mt][2] = __float_as_uint(lo.y); a[mt][3] = __float_as_uint(hi.y);
            }
            #pragma unroll
            for (int nt = 0; nt < 8; ++nt) {
                float2 bv = *(const float2*)(Bs + (warpN * 64 + nt * 8 + g) * 72 + ko);
                b[nt][0] = __float_as_uint(bv.x); b[nt][1] = __float_as_uint(bv.y);
            }
            #pragma unroll
            for (int mt = 0; mt < 2; ++mt)
                #pragma unroll
                for (int nt = 0; nt < 8; ++nt)
                    mma8(acc[mt][nt], a[mt], b[nt]);
        }
    }

    // ---- epilogue: contract against v, reduce over q4 quad, direct store ----
    const int w = blockIdx.y * 2 + warpN;
    #pragma unroll
    for (int mt = 0; mt < 2; ++mt) {
        int ra = warpM * 32 + mt * 16 + g;      // CTA-local rows
        int rb = ra + 8;
        float p[2][3] = {{0,0,0},{0,0,0}};
        #pragma unroll
        for (int nt = 0; nt < 8; ++nt) {
            int m0 = nt * 8 + q4 * 2;
            const float* va = Vs + ra * 194 + 3 * m0;
            const float* vb = Vs + rb * 194 + 3 * m0;
            float2 va01 = *(const float2*)(va);
            float2 va23 = *(const float2*)(va + 2);
            float2 va45 = *(const float2*)(va + 4);
            float2 vb01 = *(const float2*)(vb);
            float2 vb23 = *(const float2*)(vb + 2);
            float2 vb45 = *(const float2*)(vb + 4);
            float c0 = acc[mt][nt][0], c1 = acc[mt][nt][1];
            float d0 = acc[mt][nt][2], d1 = acc[mt][nt][3];
            p[0][0] += c0 * va01.x + c1 * va23.y;
            p[0][1] += c0 * va01.y + c1 * va45.x;
            p[0][2] += c0 * va23.x + c1 * va45.y;
            p[1][0] += d0 * vb01.x + d1 * vb23.y;
            p[1][1] += d0 * vb01.y + d1 * vb45.x;
            p[1][2] += d0 * vb23.x + d1 * vb45.y;
        }
        #pragma unroll
        for (int rr = 0; rr < 2; ++rr)
            #pragma unroll
            for (int k = 0; k < 3; ++k) {
                p[rr][k] += __shfl_xor_sync(0xFFFFFFFF, p[rr][k], 1);
                p[rr][k] += __shfl_xor_sync(0xFFFFFFFF, p[rr][k], 2);
            }
        if (q4 == 0) {
            const float sc = 0.015625f;   // 1/64 == C3/sqrt(3)
            float* oa = out + (size_t)(z0 + ra) * NOUT + 64 + w * 3;
            float* ob = out + (size_t)(z0 + rb) * NOUT + 64 + w * 3;
            oa[0] = p[0][0] * sc; oa[1] = p[0][1] * sc; oa[2] = p[0][2] * sc;
            ob[0] = p[1][0] * sc; ob[1] = p[1][1] * sc; ob[2] = p[1][2] * sc;
        }
    }
}

// ===================== launch =====================
extern "C" void kernel_launch(void* const* d_in, const int* in_sizes, int n_in,
                              void* d_out, int out_size) {
    const float* x  = (const float*)d_in[0];
    const float* w1 = (const float*)d_in[1];
    const float* w2 = (const float*)d_in[2];
    const float* w3 = (const float*)d_in[3];
    const float* w4 = (const float*)d_in[4];
    const float* w5 = (const float*)d_in[5];
    const float* w6 = (const float*)d_in[6];
    float* out = (float*)d_out;

    float c1  = (float)sqrt(1.0 / 4160.0);     // C1
    float c2  = (float)sqrt(1.0 / 12480.0);    // C2 == C4/sqrt(3)
    float c5s = (float)sqrt(1.0 / 62400.0);    // C5/sqrt(3)
    float c6s = (float)sqrt(1.0 / 4032.0);     // C6/sqrt(6)

    const int MAIN_SMEM = 50176 * 4 + NG0 * 2;                  // 201,888
    const int TG_SMEM   = (2 * 128 * 72 + 128 * 194) * 4;       // 173,056
    cudaFuncSetAttribute(main_kernel<0>, cudaFuncAttributeMaxDynamicSharedMemorySize, MAIN_SMEM);
    cudaFuncSetAttribute(main_kernel<2>, cudaFuncAttributeMaxDynamicSharedMemorySize, MAIN_SMEM);
    cudaFuncSetAttribute(tgemm_kernel,   cudaFuncAttributeMaxDynamicSharedMemorySize, TG_SMEM);

    cudaMemsetAsync(d_out, 0, (size_t)out_size * sizeof(float));
    init_tables_kernel<<<1, 64>>>();
    const int NTOT = 64 * K0TOT + 64 * K2TOT + 4096 * 64;
    prep_w_kernel<<<(NTOT + 255) / 256, 256>>>(w1, w2, w3, w4, w5, w6, c1, c2, c5s, c6s);

    main_kernel<2><<<dim3(64, 6), 512, MAIN_SMEM>>>(x, out);  // out2: 3 comps x 2 K-splits
    main_kernel<0><<<dim3(64, 4), 512, MAIN_SMEM>>>(x, out);  // out0: 4 K-splits
    tgemm_kernel<<<dim3(64, 32), 256, TG_SMEM>>>(x, out);     // out1 (fused contraction)
}

// round 10
// speedup vs baseline: 1.3688x; 1.0667x over previous
#include <cuda_runtime.h>
#include <cstdint>
#include <cmath>

#define ZDIM 8192
#define NOUT 448

#define K0TOT 4736          // out0 padded K (592 groups)
#define K2TOT 2304          // out2 padded K (288 groups)
#define NG0   592
#define NG2   288

// ===================== device globals (no allocation) =====================
static __device__ float g_B0t[64 * K0TOT];         // out0 weights [w][k'], prescaled + tf32
static __device__ float g_B6t[64 * K2TOT];         // out2 weights [w][k'], prescaled + tf32
static __device__ float g_B3p[4096 * 64];          // out1 weights [n=(w*64+m)][u], tf32
static __device__ unsigned short g_desc0[NG0];     // group descriptors: type<<12|u<<6|v0
static __device__ unsigned short g_desc2[NG2];

// ===================== helpers =====================
__device__ __forceinline__ uint32_t rna(float f) {
    uint32_t r; asm("cvt.rna.tf32.f32 %0, %1;" : "=r"(r) : "f"(f)); return r;
}
__device__ __forceinline__ float u2f(uint32_t u) { return __uint_as_float(u); }
__device__ __forceinline__ uint32_t smem_u32(const void* p) {
    uint32_t a;
    asm("{ .reg .u64 t; cvta.to.shared.u64 t, %1; cvt.u32.u64 %0, t; }" : "=r"(a) : "l"(p));
    return a;
}
__device__ __forceinline__ void mma8(float* c, const uint32_t* a, const uint32_t* b) {
    asm volatile("mma.sync.aligned.m16n8k8.row.col.f32.tf32.tf32.f32 "
        "{%0,%1,%2,%3}, {%4,%5,%6,%7}, {%8,%9}, {%0,%1,%2,%3};"
        : "+f"(c[0]), "+f"(c[1]), "+f"(c[2]), "+f"(c[3])
        : "r"(a[0]), "r"(a[1]), "r"(a[2]), "r"(a[3]), "r"(b[0]), "r"(b[1]));
}
__device__ __forceinline__ void ldm_x4(uint32_t* r, uint32_t addr) {
    asm volatile("ldmatrix.sync.aligned.m8n8.x4.shared.b16 {%0,%1,%2,%3}, [%4];"
        : "=r"(r[0]), "=r"(r[1]), "=r"(r[2]), "=r"(r[3]) : "r"(addr));
}
__device__ __forceinline__ void ldm_x2(uint32_t* r, uint32_t addr) {
    asm volatile("ldmatrix.sync.aligned.m8n8.x2.shared.b16 {%0,%1}, [%2];"
        : "=r"(r[0]), "=r"(r[1]) : "r"(addr));
}
__device__ __forceinline__ int triq(int u, int v) {   // triu index, valid v>u
    return u * 63 - (u * (u - 1)) / 2 + (v - u - 1);
}

// ===================== setup kernels =====================
__global__ void init_tables_kernel() {
    int u = threadIdx.x;  // 64 threads
    if (u < 63) {
        int B = u >> 3, r = u & 7;
        int cum = 8 * (8 * B - (B * (B - 1)) / 2) + r * (8 - B);
        int cnt = 8 - B;
        for (int t = 0; t < cnt; ++t) {
            int v0 = 8 * (B + t);
            g_desc0[cum + t]       = (unsigned short)((0 << 12) | (u << 6) | v0);  // ss
            g_desc0[295 + cum + t] = (unsigned short)((2 << 12) | (u << 6) | v0);  // vdot
            g_desc2[cum + t]       = (unsigned short)((0 << 12) | (u << 6) | v0);  // cross
        }
    }
    if (u < 8) {
        g_desc0[287 + u] = (unsigned short)((1 << 12) | (8 * u));   // s^2 octet
        g_desc0[582 + u] = (unsigned short)((3 << 12) | (8 * u));   // |v|^2 octet
    }
    if (u < 2) g_desc0[590 + u] = (unsigned short)(4 << 12);        // pad
    if (u == 0) g_desc2[287] = (unsigned short)(4 << 12);           // pad
}

__global__ void prep_w_kernel(const float* __restrict__ w1, const float* __restrict__ w2,
                              const float* __restrict__ w3, const float* __restrict__ w4,
                              const float* __restrict__ w5, const float* __restrict__ w6,
                              float c1, float c2, float c5s, float c6s) {
    int i = blockIdx.x * blockDim.x + threadIdx.x;
    const int N0 = 64 * K0TOT, N1 = 64 * K2TOT, N2 = 4096 * 64;
    if (i < N0) {
        int w = i / K0TOT, k = i - w * K0TOT;
        unsigned d = g_desc0[k >> 3];
        int ty = d >> 12, u = (d >> 6) & 63, v = (d & 63) + (k & 7);
        float val = 0.0f;
        if (ty == 0)      { if (v > u) val = c1  * w1[triq(u, v) * 64 + w]; }
        else if (ty == 1) { val = c2  * w2[v * 64 + w]; }
        else if (ty == 2) { if (v > u) val = c2  * w4[triq(u, v) * 64 + w]; }
        else if (ty == 3) { val = c5s * w5[v * 64 + w]; }
        g_B0t[i] = u2f(rna(val));
    } else if (i < N0 + N1) {
        int j = i - N0;
        int w = j / K2TOT, k = j - w * K2TOT;
        unsigned d = g_desc2[k >> 3];
        int ty = d >> 12, u = (d >> 6) & 63, v = (d & 63) + (k & 7);
        float val = 0.0f;
        if (ty == 0 && v > u) val = c6s * w6[triq(u, v) * 64 + w];
        g_B6t[j] = u2f(rna(val));
    } else if (i < N0 + N1 + N2) {
        int j = i - N0 - N1;
        int n = j >> 6, u = j & 63;                  // n = w*64 + m
        int w = n >> 6, m = n & 63;
        g_B3p[j] = u2f(rna(w3[(size_t)u * 4096 + m * 64 + w]));
    }
}

// ===================== main fused kernel (templated, 256 threads, 64z CTA) ================
// CTA 64z x 64w, 8 warps, warp tile 32M x 16N (2M x 4N). A plain stride 44, B plain stride 36,
// fragments via ldmatrix. x SoA planes stride 68. ~109KB smem -> 2 CTAs/SM.
template<int MODE>
__global__ __launch_bounds__(256) void main_kernel(const float* __restrict__ x,
                                                   float* __restrict__ out) {
    // float offsets
    const int AS_OFF = 0;        const int ABUF = 64 * 44;    // 2816
    const int BS_OFF = 5632;     const int BBUF = 64 * 36;    // 2304
    const int S_OFF  = 10240;
    const int VX_OFF = 14592;
    const int VY_OFF = 18944;
    const int VZ_OFF = 23296;
    const int DSC_OFF = 27648;
    extern __shared__ __align__(16) float dsm[];
    unsigned short* dsc = (unsigned short*)(dsm + DSC_OFF);

    const int tid = threadIdx.x, lane = tid & 31, wid = tid >> 5;
    const int warpM = wid & 1, warpN = wid >> 1;     // 2M x 4N
    const int g = lane >> 2, q4 = lane & 3;
    const int z0 = blockIdx.x * 64;
    const int y = blockIdx.y;

    int NCH, kofs, kz = 0;
    if (MODE == 0) { NCH = 37; kofs = y * 1184; }
    else           { NCH = 36; kz = y >> 1; kofs = (y & 1) * 1152; }
    const int gbase = kofs >> 3;
    const int LDB = (MODE == 0) ? K0TOT : K2TOT;
    const float* Bsrc = (MODE == 0) ? g_B0t : g_B6t;
    const int ca = (kz + 1) % 3, cb = (kz + 2) % 3;
    const int NG = (MODE == 0) ? NG0 : NG2;

    // ---- stage x tile SoA + descriptor table ----
    {
        int col = tid;
        int c = col - 64;
        int m = (c >= 0) ? (c / 3) : 0;
        int k3 = c - m * 3;
        int dstoff;
        if (col < 64)       dstoff = S_OFF + col;
        else if (k3 == 0)   dstoff = VX_OFF + m;
        else if (k3 == 1)   dstoff = VY_OFF + m;
        else                dstoff = VZ_OFF + m;
        #pragma unroll 4
        for (int j = 0; j < 64; ++j)
            dsm[dstoff + j * 68] = x[(size_t)(z0 + j) * 256 + col];
    }
    for (int i = tid; i < NG; i += 256)
        dsc[i] = (MODE == 0) ? g_desc0[i] : g_desc2[i];

    const int row = tid >> 2, h = tid & 3;           // 64 rows x 4 groups/chunk
    const float* Sp  = dsm + S_OFF  + row * 68;
    const float* pvx = dsm + VX_OFF + row * 68;
    const float* pvy = dsm + VY_OFF + row * 68;
    const float* pvz = dsm + VZ_OFF + row * 68;
    const float* Pca = dsm + ((ca == 0) ? VX_OFF : (ca == 1) ? VY_OFF : VZ_OFF) + row * 68;
    const float* Pcb = dsm + ((cb == 0) ? VX_OFF : (cb == 1) ? VY_OFF : VZ_OFF) + row * 68;
    const int brow = tid >> 2, bc = tid & 3;         // B stage: 64 rows, 2 float4 each
    const float* bbase = Bsrc + (size_t)brow * LDB + kofs;

    // ldmatrix lane-static bases (bytes, shared space)
    const uint32_t smem0 = smem_u32(dsm);
    const uint32_t aBase = smem0 + ((warpM * 32 + (lane & 15)) * 44 + (lane >> 4) * 4) * 4;
    const uint32_t bBase = smem0 + BS_OFF * 4
                         + ((warpN * 16 + (lane & 7)) * 36 + ((lane >> 3) & 1) * 4) * 4;

    float acc[2][2][4];
    #pragma unroll
    for (int mt = 0; mt < 2; ++mt)
        #pragma unroll
        for (int nt = 0; nt < 2; ++nt)
            #pragma unroll
            for (int j = 0; j < 4; ++j) acc[mt][nt][j] = 0.0f;

    uint32_t fr[8];
    float4 rb0, rb1;

    #define GEN(CC) do {                                                          \
        unsigned d = dsc[gbase + (CC) * 4 + h];                                   \
        int ty = d >> 12, uu = (d >> 6) & 63, v0 = d & 63;                        \
        float f[8];                                                               \
        if (MODE == 0 && ty <= 1) {                                               \
            float4 p  = *(const float4*)(Sp + v0);                                \
            float4 p2 = *(const float4*)(Sp + v0 + 4);                            \
            if (ty == 0) {                                                        \
                float su = Sp[uu];                                                \
                f[0]=su*p.x;  f[1]=su*p.y;  f[2]=su*p.z;  f[3]=su*p.w;            \
                f[4]=su*p2.x; f[5]=su*p2.y; f[6]=su*p2.z; f[7]=su*p2.w;           \
            } else {                                                              \
                f[0]=p.x*p.x;   f[1]=p.y*p.y;   f[2]=p.z*p.z;   f[3]=p.w*p.w;     \
                f[4]=p2.x*p2.x; f[5]=p2.y*p2.y; f[6]=p2.z*p2.z; f[7]=p2.w*p2.w;   \
            }                                                                     \
        } else if (MODE == 0 && ty <= 3) {                                        \
            float4 xa = *(const float4*)(pvx + v0), xb = *(const float4*)(pvx + v0 + 4); \
            float4 ya = *(const float4*)(pvy + v0), yb = *(const float4*)(pvy + v0 + 4); \
            float4 za = *(const float4*)(pvz + v0), zb = *(const float4*)(pvz + v0 + 4); \
            if (ty == 2) {                                                        \
                float ax = pvx[uu], ay = pvy[uu], az = pvz[uu];                   \
                f[0]=ax*xa.x+ay*ya.x+az*za.x; f[1]=ax*xa.y+ay*ya.y+az*za.y;       \
                f[2]=ax*xa.z+ay*ya.z+az*za.z; f[3]=ax*xa.w+ay*ya.w+az*za.w;       \
                f[4]=ax*xb.x+ay*yb.x+az*zb.x; f[5]=ax*xb.y+ay*yb.y+az*zb.y;       \
                f[6]=ax*xb.z+ay*yb.z+az*zb.z; f[7]=ax*xb.w+ay*yb.w+az*zb.w;       \
            } else {                                                              \
                f[0]=xa.x*xa.x+ya.x*ya.x+za.x*za.x; f[1]=xa.y*xa.y+ya.y*ya.y+za.y*za.y; \
                f[2]=xa.z*xa.z+ya.z*ya.z+za.z*za.z; f[3]=xa.w*xa.w+ya.w*ya.w+za.w*za.w; \
                f[4]=xb.x*xb.x+yb.x*yb.x+zb.x*zb.x; f[5]=xb.y*xb.y+yb.y*yb.y+zb.y*zb.y; \
                f[6]=xb.z*xb.z+yb.z*yb.z+zb.z*zb.z; f[7]=xb.w*xb.w+yb.w*yb.w+zb.w*zb.w; \
            }                                                                     \
        } else if (MODE == 2 && ty == 0) {                                        \
            float4 A0 = *(const float4*)(Pca + v0), A1 = *(const float4*)(Pca + v0 + 4); \
            float4 B0 = *(const float4*)(Pcb + v0), B1 = *(const float4*)(Pcb + v0 + 4); \
            float a0 = Pca[uu], a1 = Pcb[uu];                                     \
            f[0]=a0*B0.x-a1*A0.x; f[1]=a0*B0.y-a1*A0.y;                           \
            f[2]=a0*B0.z-a1*A0.z; f[3]=a0*B0.w-a1*A0.w;                           \
            f[4]=a0*B1.x-a1*A1.x; f[5]=a0*B1.y-a1*A1.y;                           \
            f[6]=a0*B1.z-a1*A1.z; f[7]=a0*B1.w-a1*A1.w;                           \
        } else {                                                                  \
            _Pragma("unroll")                                                     \
            for (int i = 0; i < 8; ++i) f[i] = 0.0f;                              \
        }                                                                         \
        _Pragma("unroll")                                                         \
        for (int i = 0; i < 8; ++i) fr[i] = rna(f[i]);                            \
    } while (0)

    // plain layout: row r, k8-block h: words = features 0..7 (matches ldmatrix frag)
    #define STORE_A(CC) do {                                                      \
        float* ap = dsm + AS_OFF + ((CC) & 1) * ABUF + row * 44 + h * 8;          \
        *(float4*)(ap)     = make_float4(u2f(fr[0]), u2f(fr[1]), u2f(fr[2]), u2f(fr[3])); \
        *(float4*)(ap + 4) = make_float4(u2f(fr[4]), u2f(fr[5]), u2f(fr[6]), u2f(fr[7])); \
    } while (0)

    #define STORE_B(CC) do {                                                      \
        float* bp = dsm + BS_OFF + ((CC) & 1) * BBUF + brow * 36;                 \
        *(float4*)(bp + bc * 4)       = rb0;                                      \
        *(float4*)(bp + (bc + 4) * 4) = rb1;                                      \
    } while (0)

    #define LOAD_B(CC) do {                                                       \
        rb0 = *(const float4*)(bbase + (CC) * 32 + bc * 4);                       \
        rb1 = *(const float4*)(bbase + (CC) * 32 + (bc + 4) * 4);                 \
    } while (0)

    // prologue: chunk 0
    __syncthreads();
    LOAD_B(0);
    GEN(0);
    STORE_A(0);
    STORE_B(0);
    __syncthreads();

    for (int c = 0; c < NCH; ++c) {
        bool more = (c + 1 < NCH);
        if (more) {
            LOAD_B(c + 1);
            GEN(c + 1);
            STORE_A(c + 1);
        }
        {
            uint32_t aT = aBase + (c & 1) * (ABUF * 4);
            uint32_t bT = bBase + (c & 1) * (BBUF * 4);
            #pragma unroll
            for (int k8 = 0; k8 < 4; ++k8) {
                uint32_t a[2][4], b[2][2];
                ldm_x4(a[0], aT + k8 * 32);
                ldm_x4(a[1], aT + 16 * 44 * 4 + k8 * 32);
                ldm_x2(b[0], bT + k8 * 32);
                ldm_x2(b[1], bT + 8 * 36 * 4 + k8 * 32);
                #pragma unroll
                for (int mt = 0; mt < 2; ++mt)
                    #pragma unroll
                    for (int nt = 0; nt < 2; ++nt)
                        mma8(acc[mt][nt], a[mt], b[nt]);
            }
        }
        if (more) STORE_B(c + 1);
        __syncthreads();
    }

    // ---- epilogue: split-K -> atomicAdd into zeroed out ----
    #pragma unroll
    for (int mt = 0; mt < 2; ++mt) {
        int za = z0 + warpM * 32 + mt * 16 + g;
        int zb = za + 8;
        #pragma unroll
        for (int nt = 0; nt < 2; ++nt) {
            int col = warpN * 16 + nt * 8 + q4 * 2;
            if (MODE == 0) {
                atomicAdd(out + (size_t)za * NOUT + col,     acc[mt][nt][0]);
                atomicAdd(out + (size_t)za * NOUT + col + 1, acc[mt][nt][1]);
                atomicAdd(out + (size_t)zb * NOUT + col,     acc[mt][nt][2]);
                atomicAdd(out + (size_t)zb * NOUT + col + 1, acc[mt][nt][3]);
            } else {
                atomicAdd(out + (size_t)za * NOUT + 256 + col * 3 + kz,       acc[mt][nt][0]);
                atomicAdd(out + (size_t)za * NOUT + 256 + (col + 1) * 3 + kz, acc[mt][nt][1]);
                atomicAdd(out + (size_t)zb * NOUT + 256 + col * 3 + kz,       acc[mt][nt][2]);
                atomicAdd(out + (size_t)zb * NOUT + 256 + (col + 1) * 3 + kz, acc[mt][nt][3]);
            }
        }
    }
    #undef GEN
    #undef STORE_A
    #undef STORE_B
    #undef LOAD_B
}

// ===================== out1 fused: CTA 64z x 128n, warp 16x64, fused v contraction ========
__global__ __launch_bounds__(256) void tgemm_kernel(const float* __restrict__ x,
                                                    float* __restrict__ out) {
    extern __shared__ __align__(16) float dsm[];
    float* As = dsm;                  // [64][72] pair-interleaved
    float* Bs = dsm + 64 * 72;        // [128][72] pair-interleaved
    float* Vs = dsm + 64 * 72 + 128 * 72;   // [64][196]

    const int tid = threadIdx.x, lane = tid & 31, wid = tid >> 5;
    const int warpM = wid & 3, warpN = wid >> 2;    // 4M x 2N
    const int g = lane >> 2, q4 = lane & 3;
    const int z0 = blockIdx.x * 64, n0 = blockIdx.y * 128;

    {   // stage A (rna(s)): 64 rows x 64 cols, pair-interleaved halves of 32
        int r = tid >> 2, seg = tid & 3;
        int hh = seg >> 1, qq = seg & 1;
        const float* srcA = x + (size_t)(z0 + r) * 256 + hh * 32;
        float* dstA = As + r * 72 + hh * 36;
        #pragma unroll
        for (int t = 0; t < 2; ++t) {
            int je = qq * 4 + t * 2;
            float4 v0 = *(const float4*)(srcA + je * 4);
            float4 v1 = *(const float4*)(srcA + je * 4 + 4);
            *(float2*)(dstA + je * 4 + 0) = make_float2(u2f(rna(v0.x)), u2f(rna(v1.x)));
            *(float2*)(dstA + je * 4 + 2) = make_float2(u2f(rna(v0.y)), u2f(rna(v1.y)));
            *(float2*)(dstA + je * 4 + 4) = make_float2(u2f(rna(v0.z)), u2f(rna(v1.z)));
            *(float2*)(dstA + je * 4 + 6) = make_float2(u2f(rna(v0.w)), u2f(rna(v1.w)));
        }
    }
    {   // stage B (already tf32): 128 rows x 64 cols
        int r = tid >> 1, hh = tid & 1;
        const float* src = g_B3p + (size_t)(n0 + r) * 64 + hh * 32;
        float* dst = Bs + r * 72 + hh * 36;
        #pragma unroll
        for (int je = 0; je < 8; je += 2) {
            float4 v0 = *(const float4*)(src + je * 4);
            float4 v1 = *(const float4*)(src + je * 4 + 4);
            *(float2*)(dst + je * 4 + 0) = make_float2(v0.x, v1.x);
            *(float2*)(dst + je * 4 + 2) = make_float2(v0.y, v1.y);
            *(float2*)(dst + je * 4 + 4) = make_float2(v0.z, v1.z);
            *(float2*)(dst + je * 4 + 6) = make_float2(v0.w, v1.w);
        }
    }
    {   // stage V: 64 rows x 192 cols, vectorized
        int r = tid >> 2, vseg = tid & 3;
        const float4* srcV = (const float4*)(x + (size_t)(z0 + r) * 256 + 64);
        float4* dstV = (float4*)(Vs + r * 196);
        #pragma unroll
        for (int t = 0; t < 12; ++t)
            dstV[vseg * 12 + t] = srcV[vseg * 12 + t];
    }
    __syncthreads();

    float acc[8][4];
    #pragma unroll
    for (int nt = 0; nt < 8; ++nt)
        #pragma unroll
        for (int j = 0; j < 4; ++j) acc[nt][j] = 0.0f;

    #pragma unroll
    for (int ch = 0; ch < 2; ++ch) {
        #pragma unroll
        for (int k8 = 0; k8 < 4; ++k8) {
            int ko = ch * 36 + k8 * 8 + q4 * 2;
            uint32_t a[4], b[8][2];
            {
                float2 lo = *(const float2*)(As + (warpM * 16 + g) * 72 + ko);
                float2 hi = *(const float2*)(As + (warpM * 16 + 8 + g) * 72 + ko);
                a[0] = __float_as_uint(lo.x); a[1] = __float_as_uint(hi.x);
                a[2] = __float_as_uint(lo.y); a[3] = __float_as_uint(hi.y);
            }
            #pragma unroll
            for (int nt = 0; nt < 8; ++nt) {
                float2 bv = *(const float2*)(Bs + (warpN * 64 + nt * 8 + g) * 72 + ko);
                b[nt][0] = __float_as_uint(bv.x); b[nt][1] = __float_as_uint(bv.y);
            }
            #pragma unroll
            for (int nt = 0; nt < 8; ++nt)
                mma8(acc[nt], a, b[nt]);
        }
    }

    // ---- epilogue: contract against v (smem), reduce over q4 quad, store ----
    const int w = blockIdx.y * 2 + warpN;
    {
        int ra = warpM * 16 + g;
        int rb = ra + 8;
        float p[2][3] = {{0,0,0},{0,0,0}};
        #pragma unroll
        for (int nt = 0; nt < 8; ++nt) {
            int m0 = nt * 8 + q4 * 2;
            const float* va = Vs + ra * 196 + 3 * m0;
            const float* vb = Vs + rb * 196 + 3 * m0;
            float2 va01 = *(const float2*)(va);
            float2 va23 = *(const float2*)(va + 2);
            float2 va45 = *(const float2*)(va + 4);
            float2 vb01 = *(const float2*)(vb);
            float2 vb23 = *(const float2*)(vb + 2);
            float2 vb45 = *(const float2*)(vb + 4);
            float c0 = acc[nt][0], c1 = acc[nt][1];
            float d0 = acc[nt][2], d1 = acc[nt][3];
            p[0][0] += c0 * va01.x + c1 * va23.y;
            p[0][1] += c0 * va01.y + c1 * va45.x;
            p[0][2] += c0 * va23.x + c1 * va45.y;
            p[1][0] += d0 * vb01.x + d1 * vb23.y;
            p[1][1] += d0 * vb01.y + d1 * vb45.x;
            p[1][2] += d0 * vb23.x + d1 * vb45.y;
        }
        #pragma unroll
        for (int rr = 0; rr < 2; ++rr)
            #pragma unroll
            for (int k = 0; k < 3; ++k) {
                p[rr][k] += __shfl_xor_sync(0xFFFFFFFF, p[rr][k], 1);
                p[rr][k] += __shfl_xor_sync(0xFFFFFFFF, p[rr][k], 2);
            }
        if (q4 == 0) {
            const float sc = 0.015625f;   // 1/64 == C3/sqrt(3)
            float* oa = out + (size_t)(z0 + ra) * NOUT + 64 + w * 3;
            float* ob = out + (size_t)(z0 + rb) * NOUT + 64 + w * 3;
            oa[0] = p[0][0] * sc; oa[1] = p[0][1] * sc; oa[2] = p[0][2] * sc;
            ob[0] = p[1][0] * sc; ob[1] = p[1][1] * sc; ob[2] = p[1][2] * sc;
        }
    }
}

// ===================== launch =====================
extern "C" void kernel_launch(void* const* d_in, const int* in_sizes, int n_in,
                              void* d_out, int out_size) {
    const float* x  = (const float*)d_in[0];
    const float* w1 = (const float*)d_in[1];
    const float* w2 = (const float*)d_in[2];
    const float* w3 = (const float*)d_in[3];
    const float* w4 = (const float*)d_in[4];
    const float* w5 = (const float*)d_in[5];
    const float* w6 = (const float*)d_in[6];
    float* out = (float*)d_out;

    float c1  = (float)sqrt(1.0 / 4160.0);     // C1
    float c2  = (float)sqrt(1.0 / 12480.0);    // C2 == C4/sqrt(3)
    float c5s = (float)sqrt(1.0 / 62400.0);    // C5/sqrt(3)
    float c6s = (float)sqrt(1.0 / 4032.0);     // C6/sqrt(6)

    const int MAIN_SMEM = 27648 * 4 + NG0 * 2;                    // 111,776
    const int TG_SMEM   = (64 * 72 + 128 * 72 + 64 * 196) * 4;    // 105,472
    cudaFuncSetAttribute(main_kernel<0>, cudaFuncAttributeMaxDynamicSharedMemorySize, MAIN_SMEM);
    cudaFuncSetAttribute(main_kernel<2>, cudaFuncAttributeMaxDynamicSharedMemorySize, MAIN_SMEM);
    cudaFuncSetAttribute(tgemm_kernel,   cudaFuncAttributeMaxDynamicSharedMemorySize, TG_SMEM);

    cudaMemsetAsync(d_out, 0, (size_t)out_size * sizeof(float));
    init_tables_kernel<<<1, 64>>>();
    const int NTOT = 64 * K0TOT + 64 * K2TOT + 4096 * 64;
    prep_w_kernel<<<(NTOT + 255) / 256, 256>>>(w1, w2, w3, w4, w5, w6, c1, c2, c5s, c6s);

    main_kernel<2><<<dim3(128, 6), 256, MAIN_SMEM>>>(x, out);  // out2: 3 comps x 2 K-splits
    main_kernel<0><<<dim3(128, 4), 256, MAIN_SMEM>>>(x, out);  // out0: 4 K-splits
    tgemm_kernel<<<dim3(128, 32), 256, TG_SMEM>>>(x, out);     // out1 (fused contraction)
}

// round 11
// speedup vs baseline: 1.5187x; 1.1095x over previous
#include <cuda_runtime.h>
#include <cstdint>
#include <cmath>

#define ZDIM 8192
#define NOUT 448

#define K0TOT 4736          // out0 padded K (592 groups)
#define K2TOT 2304          // out2 padded K (288 groups)
#define NG0   592
#define NG2   288

// ===================== device globals (no allocation) =====================
static __device__ float g_B0t[64 * K0TOT];         // out0 weights [w][k'], prescaled + tf32
static __device__ float g_B6t[64 * K2TOT];         // out2 weights [w][k'], prescaled + tf32
static __device__ float g_B3p[4096 * 64];          // out1 weights [n=(w*64+m)][u], tf32
static __device__ unsigned short g_desc0[NG0];     // group descriptors: type<<12|u<<6|v0
static __device__ unsigned short g_desc2[NG2];

// ===================== helpers =====================
__device__ __forceinline__ uint32_t rna(float f) {
    uint32_t r; asm("cvt.rna.tf32.f32 %0, %1;" : "=r"(r) : "f"(f)); return r;
}
__device__ __forceinline__ float u2f(uint32_t u) { return __uint_as_float(u); }
__device__ __forceinline__ uint32_t smem_u32(const void* p) {
    uint32_t a;
    asm("{ .reg .u64 t; cvta.to.shared.u64 t, %1; cvt.u32.u64 %0, t; }" : "=r"(a) : "l"(p));
    return a;
}
__device__ __forceinline__ void mma8(float* c, const uint32_t* a, const uint32_t* b) {
    asm volatile("mma.sync.aligned.m16n8k8.row.col.f32.tf32.tf32.f32 "
        "{%0,%1,%2,%3}, {%4,%5,%6,%7}, {%8,%9}, {%0,%1,%2,%3};"
        : "+f"(c[0]), "+f"(c[1]), "+f"(c[2]), "+f"(c[3])
        : "r"(a[0]), "r"(a[1]), "r"(a[2]), "r"(a[3]), "r"(b[0]), "r"(b[1]));
}
__device__ __forceinline__ void ldm_x4(uint32_t* r, uint32_t addr) {
    asm volatile("ldmatrix.sync.aligned.m8n8.x4.shared.b16 {%0,%1,%2,%3}, [%4];"
        : "=r"(r[0]), "=r"(r[1]), "=r"(r[2]), "=r"(r[3]) : "r"(addr));
}
__device__ __forceinline__ void ldm_x2(uint32_t* r, uint32_t addr) {
    asm volatile("ldmatrix.sync.aligned.m8n8.x2.shared.b16 {%0,%1}, [%2];"
        : "=r"(r[0]), "=r"(r[1]) : "r"(addr));
}
__device__ __forceinline__ int triq(int u, int v) {   // triu index, valid v>u
    return u * 63 - (u * (u - 1)) / 2 + (v - u - 1);
}

// ===================== setup kernels =====================
__global__ void init_tables_kernel() {
    int u = threadIdx.x;  // 64 threads
    if (u < 63) {
        int B = u >> 3, r = u & 7;
        int cum = 8 * (8 * B - (B * (B - 1)) / 2) + r * (8 - B);
        int cnt = 8 - B;
        for (int t = 0; t < cnt; ++t) {
            int v0 = 8 * (B + t);
            g_desc0[cum + t]       = (unsigned short)((0 << 12) | (u << 6) | v0);  // ss
            g_desc0[295 + cum + t] = (unsigned short)((2 << 12) | (u << 6) | v0);  // vdot
            g_desc2[cum + t]       = (unsigned short)((0 << 12) | (u << 6) | v0);  // cross
        }
    }
    if (u < 8) {
        g_desc0[287 + u] = (unsigned short)((1 << 12) | (8 * u));   // s^2 octet
        g_desc0[582 + u] = (unsigned short)((3 << 12) | (8 * u));   // |v|^2 octet
    }
    if (u < 2) g_desc0[590 + u] = (unsigned short)(4 << 12);        // pad
    if (u == 0) g_desc2[287] = (unsigned short)(4 << 12);           // pad
}

__global__ void prep_w_kernel(const float* __restrict__ w1, const float* __restrict__ w2,
                              const float* __restrict__ w3, const float* __restrict__ w4,
                              const float* __restrict__ w5, const float* __restrict__ w6,
                              float c1, float c2, float c5s, float c6s) {
    int i = blockIdx.x * blockDim.x + threadIdx.x;
    const int N0 = 64 * K0TOT, N1 = 64 * K2TOT, N2 = 4096 * 64;
    if (i < N0) {
        int w = i / K0TOT, k = i - w * K0TOT;
        unsigned d = g_desc0[k >> 3];
        int ty = d >> 12, u = (d >> 6) & 63, v = (d & 63) + (k & 7);
        float val = 0.0f;
        if (ty == 0)      { if (v > u) val = c1  * w1[triq(u, v) * 64 + w]; }
        else if (ty == 1) { val = c2  * w2[v * 64 + w]; }
        else if (ty == 2) { if (v > u) val = c2  * w4[triq(u, v) * 64 + w]; }
        else if (ty == 3) { val = c5s * w5[v * 64 + w]; }
        g_B0t[i] = u2f(rna(val));
    } else if (i < N0 + N1) {
        int j = i - N0;
        int w = j / K2TOT, k = j - w * K2TOT;
        unsigned d = g_desc2[k >> 3];
        int ty = d >> 12, u = (d >> 6) & 63, v = (d & 63) + (k & 7);
        float val = 0.0f;
        if (ty == 0 && v > u) val = c6s * w6[triq(u, v) * 64 + w];
        g_B6t[j] = u2f(rna(val));
    } else if (i < N0 + N1 + N2) {
        int j = i - N0 - N1;
        int n = j >> 6, u = j & 63;                  // n = w*64 + m
        int w = n >> 6, m = n & 63;
        g_B3p[j] = u2f(rna(w3[(size_t)u * 4096 + m * 64 + w]));
    }
}

// ===================== main fused kernel (templated, 256 threads, 64z CTA) ================
// CTA 64z x 64w, 8 warps, warp tile 32M x 16N (2M x 4N). A plain stride 44, B plain stride 36,
// fragments via ldmatrix. x SoA planes stride 68. ~109KB smem -> 2 CTAs/SM.
template<int MODE>
__global__ __launch_bounds__(256) void main_kernel(const float* __restrict__ x,
                                                   float* __restrict__ out) {
    // float offsets
    const int AS_OFF = 0;        const int ABUF = 64 * 44;    // 2816
    const int BS_OFF = 5632;     const int BBUF = 64 * 36;    // 2304
    const int S_OFF  = 10240;
    const int VX_OFF = 14592;
    const int VY_OFF = 18944;
    const int VZ_OFF = 23296;
    const int DSC_OFF = 27648;
    extern __shared__ __align__(16) float dsm[];
    unsigned short* dsc = (unsigned short*)(dsm + DSC_OFF);

    const int tid = threadIdx.x, lane = tid & 31, wid = tid >> 5;
    const int warpM = wid & 1, warpN = wid >> 1;     // 2M x 4N
    const int g = lane >> 2, q4 = lane & 3;
    const int z0 = blockIdx.x * 64;
    const int y = blockIdx.y;

    int NCH, kofs, kz = 0;
    if (MODE == 0) { NCH = 37; kofs = y * 1184; }
    else           { NCH = 36; kz = y >> 1; kofs = (y & 1) * 1152; }
    const int gbase = kofs >> 3;
    const int LDB = (MODE == 0) ? K0TOT : K2TOT;
    const float* Bsrc = (MODE == 0) ? g_B0t : g_B6t;
    const int ca = (kz + 1) % 3, cb = (kz + 2) % 3;
    const int NG = (MODE == 0) ? NG0 : NG2;

    // ---- stage x tile SoA + descriptor table ----
    {
        int col = tid;
        int c = col - 64;
        int m = (c >= 0) ? (c / 3) : 0;
        int k3 = c - m * 3;
        int dstoff = -1;
        if (MODE == 0) {
            if (col < 64)       dstoff = S_OFF + col;
            else if (k3 == 0)   dstoff = VX_OFF + m;
            else if (k3 == 1)   dstoff = VY_OFF + m;
            else                dstoff = VZ_OFF + m;
        } else {
            // only the two needed component planes
            if (col >= 64 && (k3 == ca || k3 == cb))
                dstoff = ((k3 == 0) ? VX_OFF : (k3 == 1) ? VY_OFF : VZ_OFF) + m;
        }
        if (dstoff >= 0) {
            #pragma unroll 4
            for (int j = 0; j < 64; ++j)
                dsm[dstoff + j * 68] = x[(size_t)(z0 + j) * 256 + col];
        }
    }
    for (int i = tid; i < NG; i += 256)
        dsc[i] = (MODE == 0) ? g_desc0[i] : g_desc2[i];

    const int row = tid >> 2, h = tid & 3;           // 64 rows x 4 groups/chunk
    const float* Sp  = dsm + S_OFF  + row * 68;
    const float* pvx = dsm + VX_OFF + row * 68;
    const float* pvy = dsm + VY_OFF + row * 68;
    const float* pvz = dsm + VZ_OFF + row * 68;
    const float* Pca = dsm + ((ca == 0) ? VX_OFF : (ca == 1) ? VY_OFF : VZ_OFF) + row * 68;
    const float* Pcb = dsm + ((cb == 0) ? VX_OFF : (cb == 1) ? VY_OFF : VZ_OFF) + row * 68;
    const int brow = tid >> 2, bc = tid & 3;         // B stage: 64 rows, 2 float4 each
    const float* bbase = Bsrc + (size_t)brow * LDB + kofs;

    // ldmatrix lane-static bases (bytes, shared space)
    const uint32_t smem0 = smem_u32(dsm);
    const uint32_t aBase = smem0 + ((warpM * 32 + (lane & 15)) * 44 + (lane >> 4) * 4) * 4;
    const uint32_t bBase = smem0 + BS_OFF * 4
                         + ((warpN * 16 + (lane & 7)) * 36 + ((lane >> 3) & 1) * 4) * 4;

    float acc[2][2][4];
    #pragma unroll
    for (int mt = 0; mt < 2; ++mt)
        #pragma unroll
        for (int nt = 0; nt < 2; ++nt)
            #pragma unroll
            for (int j = 0; j < 4; ++j) acc[mt][nt][j] = 0.0f;

    uint32_t fr[8];
    float4 rb0, rb1;

    #define GEN(CC) do {                                                          \
        unsigned d = dsc[gbase + (CC) * 4 + h];                                   \
        int ty = d >> 12, uu = (d >> 6) & 63, v0 = d & 63;                        \
        float f[8];                                                               \
        if (MODE == 0 && ty <= 1) {                                               \
            float4 p  = *(const float4*)(Sp + v0);                                \
            float4 p2 = *(const float4*)(Sp + v0 + 4);                            \
            if (ty == 0) {                                                        \
                float su = Sp[uu];                                                \
                f[0]=su*p.x;  f[1]=su*p.y;  f[2]=su*p.z;  f[3]=su*p.w;            \
                f[4]=su*p2.x; f[5]=su*p2.y; f[6]=su*p2.z; f[7]=su*p2.w;           \
            } else {                                                              \
                f[0]=p.x*p.x;   f[1]=p.y*p.y;   f[2]=p.z*p.z;   f[3]=p.w*p.w;     \
                f[4]=p2.x*p2.x; f[5]=p2.y*p2.y; f[6]=p2.z*p2.z; f[7]=p2.w*p2.w;   \
            }                                                                     \
        } else if (MODE == 0 && ty <= 3) {                                        \
            float4 xa = *(const float4*)(pvx + v0), xb = *(const float4*)(pvx + v0 + 4); \
            float4 ya = *(const float4*)(pvy + v0), yb = *(const float4*)(pvy + v0 + 4); \
            float4 za = *(const float4*)(pvz + v0), zb = *(const float4*)(pvz + v0 + 4); \
            if (ty == 2) {                                                        \
                float ax = pvx[uu], ay = pvy[uu], az = pvz[uu];                   \
                f[0]=ax*xa.x+ay*ya.x+az*za.x; f[1]=ax*xa.y+ay*ya.y+az*za.y;       \
                f[2]=ax*xa.z+ay*ya.z+az*za.z; f[3]=ax*xa.w+ay*ya.w+az*za.w;       \
                f[4]=ax*xb.x+ay*yb.x+az*zb.x; f[5]=ax*xb.y+ay*yb.y+az*zb.y;       \
                f[6]=ax*xb.z+ay*yb.z+az*zb.z; f[7]=ax*xb.w+ay*yb.w+az*zb.w;       \
            } else {                                                              \
                f[0]=xa.x*xa.x+ya.x*ya.x+za.x*za.x; f[1]=xa.y*xa.y+ya.y*ya.y+za.y*za.y; \
                f[2]=xa.z*xa.z+ya.z*ya.z+za.z*za.z; f[3]=xa.w*xa.w+ya.w*ya.w+za.w*za.w; \
                f[4]=xb.x*xb.x+yb.x*yb.x+zb.x*zb.x; f[5]=xb.y*xb.y+yb.y*yb.y+zb.y*zb.y; \
                f[6]=xb.z*xb.z+yb.z*yb.z+zb.z*zb.z; f[7]=xb.w*xb.w+yb.w*yb.w+zb.w*zb.w; \
            }                                                                     \
        } else if (MODE == 2 && ty == 0) {                                        \
            float4 A0 = *(const float4*)(Pca + v0), A1 = *(const float4*)(Pca + v0 + 4); \
            float4 B0 = *(const float4*)(Pcb + v0), B1 = *(const float4*)(Pcb + v0 + 4); \
            float a0 = Pca[uu], a1 = Pcb[uu];                                     \
            f[0]=a0*B0.x-a1*A0.x; f[1]=a0*B0.y-a1*A0.y;                           \
            f[2]=a0*B0.z-a1*A0.z; f[3]=a0*B0.w-a1*A0.w;                           \
            f[4]=a0*B1.x-a1*A1.x; f[5]=a0*B1.y-a1*A1.y;                           \
            f[6]=a0*B1.z-a1*A1.z; f[7]=a0*B1.w-a1*A1.w;                           \
        } else {                                                                  \
            _Pragma("unroll")                                                     \
            for (int i = 0; i < 8; ++i) f[i] = 0.0f;                              \
        }                                                                         \
        _Pragma("unroll")                                                         \
        for (int i = 0; i < 8; ++i) fr[i] = rna(f[i]);                            \
    } while (0)

    #define STORE_A(CC) do {                                                      \
        float* ap = dsm + AS_OFF + ((CC) & 1) * ABUF + row * 44 + h * 8;          \
        *(float4*)(ap)     = make_float4(u2f(fr[0]), u2f(fr[1]), u2f(fr[2]), u2f(fr[3])); \
        *(float4*)(ap + 4) = make_float4(u2f(fr[4]), u2f(fr[5]), u2f(fr[6]), u2f(fr[7])); \
    } while (0)

    #define STORE_B(CC) do {                                                      \
        float* bp = dsm + BS_OFF + ((CC) & 1) * BBUF + brow * 36;                 \
        *(float4*)(bp + bc * 4)       = rb0;                                      \
        *(float4*)(bp + (bc + 4) * 4) = rb1;                                      \
    } while (0)

    #define LOAD_B(CC) do {                                                       \
        rb0 = *(const float4*)(bbase + (CC) * 32 + bc * 4);                       \
        rb1 = *(const float4*)(bbase + (CC) * 32 + (bc + 4) * 4);                 \
    } while (0)

    // prologue: chunk 0
    __syncthreads();
    LOAD_B(0);
    GEN(0);
    STORE_A(0);
    STORE_B(0);
    __syncthreads();

    for (int c = 0; c < NCH; ++c) {
        bool more = (c + 1 < NCH);
        if (more) {
            LOAD_B(c + 1);
            GEN(c + 1);
            STORE_A(c + 1);
        }
        {
            uint32_t aT = aBase + (c & 1) * (ABUF * 4);
            uint32_t bT = bBase + (c & 1) * (BBUF * 4);
            #pragma unroll
            for (int k8 = 0; k8 < 4; ++k8) {
                uint32_t a[2][4], b[2][2];
                ldm_x4(a[0], aT + k8 * 32);
                ldm_x4(a[1], aT + 16 * 44 * 4 + k8 * 32);
                ldm_x2(b[0], bT + k8 * 32);
                ldm_x2(b[1], bT + 8 * 36 * 4 + k8 * 32);
                #pragma unroll
                for (int mt = 0; mt < 2; ++mt)
                    #pragma unroll
                    for (int nt = 0; nt < 2; ++nt)
                        mma8(acc[mt][nt], a[mt], b[nt]);
            }
        }
        if (more) STORE_B(c + 1);
        __syncthreads();
    }

    // ---- epilogue: split-K -> atomicAdd into zeroed out ----
    #pragma unroll
    for (int mt = 0; mt < 2; ++mt) {
        int za = z0 + warpM * 32 + mt * 16 + g;
        int zb = za + 8;
        #pragma unroll
        for (int nt = 0; nt < 2; ++nt) {
            int col = warpN * 16 + nt * 8 + q4 * 2;
            if (MODE == 0) {
                atomicAdd(out + (size_t)za * NOUT + col,     acc[mt][nt][0]);
                atomicAdd(out + (size_t)za * NOUT + col + 1, acc[mt][nt][1]);
                atomicAdd(out + (size_t)zb * NOUT + col,     acc[mt][nt][2]);
                atomicAdd(out + (size_t)zb * NOUT + col + 1, acc[mt][nt][3]);
            } else {
                atomicAdd(out + (size_t)za * NOUT + 256 + col * 3 + kz,       acc[mt][nt][0]);
                atomicAdd(out + (size_t)za * NOUT + 256 + (col + 1) * 3 + kz, acc[mt][nt][1]);
                atomicAdd(out + (size_t)zb * NOUT + 256 + col * 3 + kz,       acc[mt][nt][2]);
                atomicAdd(out + (size_t)zb * NOUT + 256 + (col + 1) * 3 + kz, acc[mt][nt][3]);
            }
        }
    }
    #undef GEN
    #undef STORE_A
    #undef STORE_B
    #undef LOAD_B
}

// ===================== out1 fused v2: z-resident CTA, loops over all 32 B-tiles ===========
// Grid 128 (one CTA per 64-z tile). 256 thr, warps 4M x 2N (wM=16, wN=64 = one w per warpN).
// A (rna(s)) and V staged ONCE; B double-buffered, prefetched in registers.
__global__ __launch_bounds__(256) void tgemm_kernel(const float* __restrict__ x,
                                                    float* __restrict__ out) {
    const int AS_OFF = 0;                    // [64][72]
    const int VS_OFF = 4608;                 // [64][196]
    const int BS_OFF = 17152;                // 2 x [128][72]
    const int BBUF   = 128 * 72;             // 9216
    extern __shared__ __align__(16) float dsm[];
    float* As = dsm + AS_OFF;
    float* Vs = dsm + VS_OFF;

    const int tid = threadIdx.x, lane = tid & 31, wid = tid >> 5;
    const int warpM = wid & 3, warpN = wid >> 2;    // 4M x 2N
    const int g = lane >> 2, q4 = lane & 3;
    const int z0 = blockIdx.x * 64;

    {   // stage A (rna(s)): 64 rows x 64 cols, pair-interleaved halves of 32
        int r = tid >> 2, seg = tid & 3;
        int hh = seg >> 1, qq = seg & 1;
        const float* srcA = x + (size_t)(z0 + r) * 256 + hh * 32;
        float* dstA = As + r * 72 + hh * 36;
        #pragma unroll
        for (int t = 0; t < 2; ++t) {
            int je = qq * 4 + t * 2;
            float4 v0 = *(const float4*)(srcA + je * 4);
            float4 v1 = *(const float4*)(srcA + je * 4 + 4);
            *(float2*)(dstA + je * 4 + 0) = make_float2(u2f(rna(v0.x)), u2f(rna(v1.x)));
            *(float2*)(dstA + je * 4 + 2) = make_float2(u2f(rna(v0.y)), u2f(rna(v1.y)));
            *(float2*)(dstA + je * 4 + 4) = make_float2(u2f(rna(v0.z)), u2f(rna(v1.z)));
            *(float2*)(dstA + je * 4 + 6) = make_float2(u2f(rna(v0.w)), u2f(rna(v1.w)));
        }
    }
    {   // stage V: 64 rows x 192 cols, vectorized
        int r = tid >> 2, vseg = tid & 3;
        const float4* srcV = (const float4*)(x + (size_t)(z0 + r) * 256 + 64);
        float4* dstV = (float4*)(Vs + r * 196);
        #pragma unroll
        for (int t = 0; t < 12; ++t)
            dstV[vseg * 12 + t] = srcV[vseg * 12 + t];
    }

    // B staging mapping: 128 rows x 64 cols per tile; thread covers (row = tid>>1, half hh)
    const int brow = tid >> 1, bhh = tid & 1;
    const float* bsrc0 = g_B3p + (size_t)brow * 64 + bhh * 32;
    float* bdst = dsm + BS_OFF + brow * 72 + bhh * 36;

    float4 rg[8];
    #define LOAD_BT(IT) do {                                                      \
        const float* s = bsrc0 + (size_t)(IT) * 128 * 64;                         \
        _Pragma("unroll")                                                         \
        for (int t = 0; t < 8; ++t) rg[t] = *(const float4*)(s + t * 4);          \
    } while (0)
    #define STORE_BT(IT) do {                                                     \
        float* d = bdst + ((IT) & 1) * BBUF;                                      \
        _Pragma("unroll")                                                         \
        for (int t = 0; t < 4; ++t) {                                             \
            *(float2*)(d + t * 8 + 0) = make_float2(rg[2*t].x, rg[2*t+1].x);      \
            *(float2*)(d + t * 8 + 2) = make_float2(rg[2*t].y, rg[2*t+1].y);      \
            *(float2*)(d + t * 8 + 4) = make_float2(rg[2*t].z, rg[2*t+1].z);      \
            *(float2*)(d + t * 8 + 6) = make_float2(rg[2*t].w, rg[2*t+1].w);      \
        }                                                                         \
    } while (0)

    LOAD_BT(0);
    STORE_BT(0);
    __syncthreads();

    const float sc = 0.015625f;   // 1/64 == C3/sqrt(3)

    for (int it = 0; it < 32; ++it) {
        if (it + 1 < 32) LOAD_BT(it + 1);

        float acc[8][4];
        #pragma unroll
        for (int nt = 0; nt < 8; ++nt)
            #pragma unroll
            for (int j = 0; j < 4; ++j) acc[nt][j] = 0.0f;

        const float* Bs = dsm + BS_OFF + (it & 1) * BBUF;
        #pragma unroll
        for (int ch = 0; ch < 2; ++ch) {
            #pragma unroll
            for (int k8 = 0; k8 < 4; ++k8) {
                int ko = ch * 36 + k8 * 8 + q4 * 2;
                uint32_t a[4], b[8][2];
                {
                    float2 lo = *(const float2*)(As + (warpM * 16 + g) * 72 + ko);
                    float2 hi = *(const float2*)(As + (warpM * 16 + 8 + g) * 72 + ko);
                    a[0] = __float_as_uint(lo.x); a[1] = __float_as_uint(hi.x);
                    a[2] = __float_as_uint(lo.y); a[3] = __float_as_uint(hi.y);
                }
                #pragma unroll
                for (int nt = 0; nt < 8; ++nt) {
                    float2 bv = *(const float2*)(Bs + (warpN * 64 + nt * 8 + g) * 72 + ko);
                    b[nt][0] = __float_as_uint(bv.x); b[nt][1] = __float_as_uint(bv.y);
                }
                #pragma unroll
                for (int nt = 0; nt < 8; ++nt)
                    mma8(acc[nt], a, b[nt]);
            }
        }

        // epilogue: contract against v, reduce over q4 quad, store
        {
            int ra = warpM * 16 + g;
            int rb = ra + 8;
            float p[2][3] = {{0,0,0},{0,0,0}};
            #pragma unroll
            for (int nt = 0; nt < 8; ++nt) {
                int m0 = nt * 8 + q4 * 2;
                const float* va = Vs + ra * 196 + 3 * m0;
                const float* vb = Vs + rb * 196 + 3 * m0;
                float2 va01 = *(const float2*)(va);
                float2 va23 = *(const float2*)(va + 2);
                float2 va45 = *(const float2*)(va + 4);
                float2 vb01 = *(const float2*)(vb);
                float2 vb23 = *(const float2*)(vb + 2);
                float2 vb45 = *(const float2*)(vb + 4);
                float c0 = acc[nt][0], c1 = acc[nt][1];
                float d0 = acc[nt][2], d1 = acc[nt][3];
                p[0][0] += c0 * va01.x + c1 * va23.y;
                p[0][1] += c0 * va01.y + c1 * va45.x;
                p[0][2] += c0 * va23.x + c1 * va45.y;
                p[1][0] += d0 * vb01.x + d1 * vb23.y;
                p[1][1] += d0 * vb01.y + d1 * vb45.x;
                p[1][2] += d0 * vb23.x + d1 * vb45.y;
            }
            #pragma unroll
            for (int rr = 0; rr < 2; ++rr)
                #pragma unroll
                for (int k = 0; k < 3; ++k) {
                    p[rr][k] += __shfl_xor_sync(0xFFFFFFFF, p[rr][k], 1);
                    p[rr][k] += __shfl_xor_sync(0xFFFFFFFF, p[rr][k], 2);
                }
            if (q4 == 0) {
                int w = it * 2 + warpN;
                float* oa = out + (size_t)(z0 + ra) * NOUT + 64 + w * 3;
                float* ob = out + (size_t)(z0 + rb) * NOUT + 64 + w * 3;
                oa[0] = p[0][0] * sc; oa[1] = p[0][1] * sc; oa[2] = p[0][2] * sc;
                ob[0] = p[1][0] * sc; ob[1] = p[1][1] * sc; ob[2] = p[1][2] * sc;
            }
        }

        if (it + 1 < 32) STORE_BT(it + 1);
        __syncthreads();
    }
    #undef LOAD_BT
    #undef STORE_BT
}

// ===================== launch =====================
extern "C" void kernel_launch(void* const* d_in, const int* in_sizes, int n_in,
                              void* d_out, int out_size) {
    const float* x  = (const float*)d_in[0];
    const float* w1 = (const float*)d_in[1];
    const float* w2 = (const float*)d_in[2];
    const float* w3 = (const float*)d_in[3];
    const float* w4 = (const float*)d_in[4];
    const float* w5 = (const float*)d_in[5];
    const float* w6 = (const float*)d_in[6];
    float* out = (float*)d_out;

    float c1  = (float)sqrt(1.0 / 4160.0);     // C1
    float c2  = (float)sqrt(1.0 / 12480.0);    // C2 == C4/sqrt(3)
    float c5s = (float)sqrt(1.0 / 62400.0);    // C5/sqrt(3)
    float c6s = (float)sqrt(1.0 / 4032.0);     // C6/sqrt(6)

    const int MAIN_SMEM = 27648 * 4 + NG0 * 2;                    // 111,776
    const int TG_SMEM   = (4608 + 12544 + 2 * 128 * 72) * 4;      // 142,336
    cudaFuncSetAttribute(main_kernel<0>, cudaFuncAttributeMaxDynamicSharedMemorySize, MAIN_SMEM);
    cudaFuncSetAttribute(main_kernel<2>, cudaFuncAttributeMaxDynamicSharedMemorySize, MAIN_SMEM);
    cudaFuncSetAttribute(tgemm_kernel,   cudaFuncAttributeMaxDynamicSharedMemorySize, TG_SMEM);

    cudaMemsetAsync(d_out, 0, (size_t)out_size * sizeof(float));
    init_tables_kernel<<<1, 64>>>();
    const int NTOT = 64 * K0TOT + 64 * K2TOT + 4096 * 64;
    prep_w_kernel<<<(NTOT + 255) / 256, 256>>>(w1, w2, w3, w4, w5, w6, c1, c2, c5s, c6s);

    main_kernel<2><<<dim3(128, 6), 256, MAIN_SMEM>>>(x, out);  // out2: 3 comps x 2 K-splits
    main_kernel<0><<<dim3(128, 4), 256, MAIN_SMEM>>>(x, out);  // out0: 4 K-splits
    tgemm_kernel<<<128, 256, TG_SMEM>>>(x, out);               // out1 (z-resident, pipelined)
}

// round 12
// speedup vs baseline: 1.7261x; 1.1365x over previous
#include <cuda_runtime.h>
#include <cstdint>
#include <cmath>

#define ZDIM 8192
#define NOUT 448

#define K0TOT 4736          // out0 padded K (592 groups)
#define K2TOT 2304          // out2 padded K (288 groups)
#define NG0   592
#define NG2   288

// ===================== device globals (no allocation) =====================
static __device__ float g_B0t[64 * K0TOT];         // out0 weights [w][k'], prescaled + tf32
static __device__ float g_B6t[64 * K2TOT];         // out2 weights [w][k'], prescaled + tf32
static __device__ float g_B3p[4096 * 64];          // out1 weights [n=(w*64+m)][u], tf32
static __device__ unsigned short g_desc0[NG0];     // group descriptors: type<<12|u<<6|v0
static __device__ unsigned short g_desc2[NG2];

// ===================== helpers =====================
__device__ __forceinline__ uint32_t rna(float f) {
    uint32_t r; asm("cvt.rna.tf32.f32 %0, %1;" : "=r"(r) : "f"(f)); return r;
}
__device__ __forceinline__ float u2f(uint32_t u) { return __uint_as_float(u); }
__device__ __forceinline__ uint32_t smem_u32(const void* p) {
    uint32_t a;
    asm("{ .reg .u64 t; cvta.to.shared.u64 t, %1; cvt.u32.u64 %0, t; }" : "=r"(a) : "l"(p));
    return a;
}
__device__ __forceinline__ void mma8(float* c, const uint32_t* a, const uint32_t* b) {
    asm volatile("mma.sync.aligned.m16n8k8.row.col.f32.tf32.tf32.f32 "
        "{%0,%1,%2,%3}, {%4,%5,%6,%7}, {%8,%9}, {%0,%1,%2,%3};"
        : "+f"(c[0]), "+f"(c[1]), "+f"(c[2]), "+f"(c[3])
        : "r"(a[0]), "r"(a[1]), "r"(a[2]), "r"(a[3]), "r"(b[0]), "r"(b[1]));
}
__device__ __forceinline__ void ldm_x4(uint32_t* r, uint32_t addr) {
    asm volatile("ldmatrix.sync.aligned.m8n8.x4.shared.b16 {%0,%1,%2,%3}, [%4];"
        : "=r"(r[0]), "=r"(r[1]), "=r"(r[2]), "=r"(r[3]) : "r"(addr));
}
__device__ __forceinline__ void ldm_x2(uint32_t* r, uint32_t addr) {
    asm volatile("ldmatrix.sync.aligned.m8n8.x2.shared.b16 {%0,%1}, [%2];"
        : "=r"(r[0]), "=r"(r[1]) : "r"(addr));
}
__device__ __forceinline__ int triq(int u, int v) {   // triu index, valid v>u
    return u * 63 - (u * (u - 1)) / 2 + (v - u - 1);
}

// ===================== setup kernels =====================
__global__ void init_tables_kernel() {
    int u = threadIdx.x;  // 64 threads
    if (u < 63) {
        int B = u >> 3, r = u & 7;
        int cum = 8 * (8 * B - (B * (B - 1)) / 2) + r * (8 - B);
        int cnt = 8 - B;
        for (int t = 0; t < cnt; ++t) {
            int v0 = 8 * (B + t);
            g_desc0[cum + t]       = (unsigned short)((0 << 12) | (u << 6) | v0);  // ss
            g_desc0[295 + cum + t] = (unsigned short)((2 << 12) | (u << 6) | v0);  // vdot
            g_desc2[cum + t]       = (unsigned short)((0 << 12) | (u << 6) | v0);  // cross
        }
    }
    if (u < 8) {
        g_desc0[287 + u] = (unsigned short)((1 << 12) | (8 * u));   // s^2 octet
        g_desc0[582 + u] = (unsigned short)((3 << 12) | (8 * u));   // |v|^2 octet
    }
    if (u < 2) g_desc0[590 + u] = (unsigned short)(4 << 12);        // pad
    if (u == 0) g_desc2[287] = (unsigned short)(4 << 12);           // pad
}

__global__ void prep_w_kernel(const float* __restrict__ w1, const float* __restrict__ w2,
                              const float* __restrict__ w3, const float* __restrict__ w4,
                              const float* __restrict__ w5, const float* __restrict__ w6,
                              float c1, float c2, float c5s, float c6s) {
    int i = blockIdx.x * blockDim.x + threadIdx.x;
    const int N0 = 64 * K0TOT, N1 = 64 * K2TOT, N2 = 4096 * 64;
    if (i < N0) {
        int w = i / K0TOT, k = i - w * K0TOT;
        unsigned d = g_desc0[k >> 3];
        int ty = d >> 12, u = (d >> 6) & 63, v = (d & 63) + (k & 7);
        float val = 0.0f;
        if (ty == 0)      { if (v > u) val = c1  * w1[triq(u, v) * 64 + w]; }
        else if (ty == 1) { val = c2  * w2[v * 64 + w]; }
        else if (ty == 2) { if (v > u) val = c2  * w4[triq(u, v) * 64 + w]; }
        else if (ty == 3) { val = c5s * w5[v * 64 + w]; }
        g_B0t[i] = u2f(rna(val));
    } else if (i < N0 + N1) {
        int j = i - N0;
        int w = j / K2TOT, k = j - w * K2TOT;
        unsigned d = g_desc2[k >> 3];
        int ty = d >> 12, u = (d >> 6) & 63, v = (d & 63) + (k & 7);
        float val = 0.0f;
        if (ty == 0 && v > u) val = c6s * w6[triq(u, v) * 64 + w];
        g_B6t[j] = u2f(rna(val));
    } else if (i < N0 + N1 + N2) {
        int j = i - N0 - N1;
        int n = j >> 6, u = j & 63;                  // n = w*64 + m
        int w = n >> 6, m = n & 63;
        g_B3p[j] = u2f(rna(w3[(size_t)u * 4096 + m * 64 + w]));
    }
}

// ===================== main body (out0 / out2) =====================
// CTA 64z x 64w, 8 warps, warp tile 32M x 16N (2M x 4N). ldmatrix fragments.
// MODE 0: out0, split-K y=0..3 (37 chunks), atomicAdd.
// MODE 2: out2, y = cross component, full K (72 chunks), direct store.
template<int MODE>
__device__ __forceinline__ void main_body(const float* __restrict__ x,
                                          float* __restrict__ out,
                                          float* dsm, int z0, int y) {
    const int AS_OFF = 0;        const int ABUF = 64 * 44;    // 2816
    const int BS_OFF = 5632;     const int BBUF = 64 * 36;    // 2304
    const int S_OFF  = 10240;
    const int VX_OFF = 14592;
    const int VY_OFF = 18944;
    const int VZ_OFF = 23296;
    const int DSC_OFF = 27648;
    unsigned short* dsc = (unsigned short*)(dsm + DSC_OFF);

    const int tid = threadIdx.x, lane = tid & 31, wid = tid >> 5;
    const int warpM = wid & 1, warpN = wid >> 1;     // 2M x 4N
    const int g = lane >> 2, q4 = lane & 3;

    int NCH, kofs, kz = 0;
    if (MODE == 0) { NCH = 37; kofs = y * 1184; }
    else           { NCH = 72; kofs = 0; kz = y; }
    const int gbase = kofs >> 3;
    const int LDB = (MODE == 0) ? K0TOT : K2TOT;
    const float* Bsrc = (MODE == 0) ? g_B0t : g_B6t;
    const int ca = (kz + 1) % 3, cb = (kz + 2) % 3;
    const int NG = (MODE == 0) ? NG0 : NG2;

    // ---- stage x tile SoA + descriptor table ----
    {
        int col = tid;
        int c = col - 64;
        int m = (c >= 0) ? (c / 3) : 0;
        int k3 = c - m * 3;
        int dstoff = -1;
        if (MODE == 0) {
            if (col < 64)       dstoff = S_OFF + col;
            else if (k3 == 0)   dstoff = VX_OFF + m;
            else if (k3 == 1)   dstoff = VY_OFF + m;
            else                dstoff = VZ_OFF + m;
        } else {
            if (col >= 64 && (k3 == ca || k3 == cb))
                dstoff = ((k3 == 0) ? VX_OFF : (k3 == 1) ? VY_OFF : VZ_OFF) + m;
        }
        if (dstoff >= 0) {
            #pragma unroll 4
            for (int j = 0; j < 64; ++j)
                dsm[dstoff + j * 68] = x[(size_t)(z0 + j) * 256 + col];
        }
    }
    for (int i = tid; i < NG; i += 256)
        dsc[i] = (MODE == 0) ? g_desc0[i] : g_desc2[i];

    const int row = tid >> 2, h = tid & 3;           // 64 rows x 4 groups/chunk
    const float* Sp  = dsm + S_OFF  + row * 68;
    const float* pvx = dsm + VX_OFF + row * 68;
    const float* pvy = dsm + VY_OFF + row * 68;
    const float* pvz = dsm + VZ_OFF + row * 68;
    const float* Pca = dsm + ((ca == 0) ? VX_OFF : (ca == 1) ? VY_OFF : VZ_OFF) + row * 68;
    const float* Pcb = dsm + ((cb == 0) ? VX_OFF : (cb == 1) ? VY_OFF : VZ_OFF) + row * 68;
    const int brow = tid >> 2, bc = tid & 3;         // B stage: 64 rows, 2 float4 each
    const float* bbase = Bsrc + (size_t)brow * LDB + kofs;

    const uint32_t smem0 = smem_u32(dsm);
    const uint32_t aBase = smem0 + ((warpM * 32 + (lane & 15)) * 44 + (lane >> 4) * 4) * 4;
    const uint32_t bBase = smem0 + BS_OFF * 4
                         + ((warpN * 16 + (lane & 7)) * 36 + ((lane >> 3) & 1) * 4) * 4;

    float acc[2][2][4];
    #pragma unroll
    for (int mt = 0; mt < 2; ++mt)
        #pragma unroll
        for (int nt = 0; nt < 2; ++nt)
            #pragma unroll
            for (int j = 0; j < 4; ++j) acc[mt][nt][j] = 0.0f;

    uint32_t fr[8];
    float4 rb0, rb1;

    #define GEN(CC) do {                                                          \
        unsigned d = dsc[gbase + (CC) * 4 + h];                                   \
        int ty = d >> 12, uu = (d >> 6) & 63, v0 = d & 63;                        \
        float f[8];                                                               \
        if (MODE == 0 && ty <= 1) {                                               \
            float4 p  = *(const float4*)(Sp + v0);                                \
            float4 p2 = *(const float4*)(Sp + v0 + 4);                            \
            if (ty == 0) {                                                        \
                float su = Sp[uu];                                                \
                f[0]=su*p.x;  f[1]=su*p.y;  f[2]=su*p.z;  f[3]=su*p.w;            \
                f[4]=su*p2.x; f[5]=su*p2.y; f[6]=su*p2.z; f[7]=su*p2.w;           \
            } else {                                                              \
                f[0]=p.x*p.x;   f[1]=p.y*p.y;   f[2]=p.z*p.z;   f[3]=p.w*p.w;     \
                f[4]=p2.x*p2.x; f[5]=p2.y*p2.y; f[6]=p2.z*p2.z; f[7]=p2.w*p2.w;   \
            }                                                                     \
        } else if (MODE == 0 && ty <= 3) {                                        \
            float4 xa = *(const float4*)(pvx + v0), xb = *(const float4*)(pvx + v0 + 4); \
            float4 ya = *(const float4*)(pvy + v0), yb = *(const float4*)(pvy + v0 + 4); \
            float4 za = *(const float4*)(pvz + v0), zb = *(const float4*)(pvz + v0 + 4); \
            if (ty == 2) {                                                        \
                float ax = pvx[uu], ay = pvy[uu], az = pvz[uu];                   \
                f[0]=ax*xa.x+ay*ya.x+az*za.x; f[1]=ax*xa.y+ay*ya.y+az*za.y;       \
                f[2]=ax*xa.z+ay*ya.z+az*za.z; f[3]=ax*xa.w+ay*ya.w+az*za.w;       \
                f[4]=ax*xb.x+ay*yb.x+az*zb.x; f[5]=ax*xb.y+ay*yb.y+az*zb.y;       \
                f[6]=ax*xb.z+ay*yb.z+az*zb.z; f[7]=ax*xb.w+ay*yb.w+az*zb.w;       \
            } else {                                                              \
                f[0]=xa.x*xa.x+ya.x*ya.x+za.x*za.x; f[1]=xa.y*xa.y+ya.y*ya.y+za.y*za.y; \
                f[2]=xa.z*xa.z+ya.z*ya.z+za.z*za.z; f[3]=xa.w*xa.w+ya.w*ya.w+za.w*za.w; \
                f[4]=xb.x*xb.x+yb.x*yb.x+zb.x*zb.x; f[5]=xb.y*xb.y+yb.y*yb.y+zb.y*zb.y; \
                f[6]=xb.z*xb.z+yb.z*yb.z+zb.z*zb.z; f[7]=xb.w*xb.w+yb.w*yb.w+zb.w*zb.w; \
            }                                                                     \
        } else if (MODE == 2 && ty == 0) {                                        \
            float4 A0 = *(const float4*)(Pca + v0), A1 = *(const float4*)(Pca + v0 + 4); \
            float4 B0 = *(const float4*)(Pcb + v0), B1 = *(const float4*)(Pcb + v0 + 4); \
            float a0 = Pca[uu], a1 = Pcb[uu];                                     \
            f[0]=a0*B0.x-a1*A0.x; f[1]=a0*B0.y-a1*A0.y;                           \
            f[2]=a0*B0.z-a1*A0.z; f[3]=a0*B0.w-a1*A0.w;                           \
            f[4]=a0*B1.x-a1*A1.x; f[5]=a0*B1.y-a1*A1.y;                           \
            f[6]=a0*B1.z-a1*A1.z; f[7]=a0*B1.w-a1*A1.w;                           \
        } else {                                                                  \
            _Pragma("unroll")                                                     \
            for (int i = 0; i < 8; ++i) f[i] = 0.0f;                              \
        }                                                                         \
        _Pragma("unroll")                                                         \
        for (int i = 0; i < 8; ++i) fr[i] = rna(f[i]);                            \
    } while (0)

    #define STORE_A(CC) do {                                                      \
        float* ap = dsm + AS_OFF + ((CC) & 1) * ABUF + row * 44 + h * 8;          \
        *(float4*)(ap)     = make_float4(u2f(fr[0]), u2f(fr[1]), u2f(fr[2]), u2f(fr[3])); \
        *(float4*)(ap + 4) = make_float4(u2f(fr[4]), u2f(fr[5]), u2f(fr[6]), u2f(fr[7])); \
    } while (0)

    #define STORE_B(CC) do {                                                      \
        float* bp = dsm + BS_OFF + ((CC) & 1) * BBUF + brow * 36;                 \
        *(float4*)(bp + bc * 4)       = rb0;                                      \
        *(float4*)(bp + (bc + 4) * 4) = rb1;                                      \
    } while (0)

    #define LOAD_B(CC) do {                                                       \
        rb0 = *(const float4*)(bbase + (CC) * 32 + bc * 4);                       \
        rb1 = *(const float4*)(bbase + (CC) * 32 + (bc + 4) * 4);                 \
    } while (0)

    __syncthreads();
    LOAD_B(0);
    GEN(0);
    STORE_A(0);
    STORE_B(0);
    __syncthreads();

    for (int c = 0; c < NCH; ++c) {
        bool more = (c + 1 < NCH);
        if (more) {
            LOAD_B(c + 1);
            GEN(c + 1);
            STORE_A(c + 1);
        }
        {
            uint32_t aT = aBase + (c & 1) * (ABUF * 4);
            uint32_t bT = bBase + (c & 1) * (BBUF * 4);
            #pragma unroll
            for (int k8 = 0; k8 < 4; ++k8) {
                uint32_t a[2][4], b[2][2];
                ldm_x4(a[0], aT + k8 * 32);
                ldm_x4(a[1], aT + 16 * 44 * 4 + k8 * 32);
                ldm_x2(b[0], bT + k8 * 32);
                ldm_x2(b[1], bT + 8 * 36 * 4 + k8 * 32);
                #pragma unroll
                for (int mt = 0; mt < 2; ++mt)
                    #pragma unroll
                    for (int nt = 0; nt < 2; ++nt)
                        mma8(acc[mt][nt], a[mt], b[nt]);
            }
        }
        if (more) STORE_B(c + 1);
        __syncthreads();
    }

    #pragma unroll
    for (int mt = 0; mt < 2; ++mt) {
        int za = z0 + warpM * 32 + mt * 16 + g;
        int zb = za + 8;
        #pragma unroll
        for (int nt = 0; nt < 2; ++nt) {
            int col = warpN * 16 + nt * 8 + q4 * 2;
            if (MODE == 0) {
                atomicAdd(out + (size_t)za * NOUT + col,     acc[mt][nt][0]);
                atomicAdd(out + (size_t)za * NOUT + col + 1, acc[mt][nt][1]);
                atomicAdd(out + (size_t)zb * NOUT + col,     acc[mt][nt][2]);
                atomicAdd(out + (size_t)zb * NOUT + col + 1, acc[mt][nt][3]);
            } else {
                out[(size_t)za * NOUT + 256 + col * 3 + kz]       = acc[mt][nt][0];
                out[(size_t)za * NOUT + 256 + (col + 1) * 3 + kz] = acc[mt][nt][1];
                out[(size_t)zb * NOUT + 256 + col * 3 + kz]       = acc[mt][nt][2];
                out[(size_t)zb * NOUT + 256 + (col + 1) * 3 + kz] = acc[mt][nt][3];
            }
        }
    }
    #undef GEN
    #undef STORE_A
    #undef STORE_B
    #undef LOAD_B
}

// ===================== out1 body: z-resident, 32 B-tiles, single-buffered B ===============
__device__ __forceinline__ void tgemm_body(const float* __restrict__ x,
                                           float* __restrict__ out,
                                           float* dsm, int z0) {
    const int AS_OFF = 0;                    // [64][72]
    const int VS_OFF = 4608;                 // [64][196]
    const int BS_OFF = 17152;                // [128][72] single buffer
    float* As = dsm + AS_OFF;
    float* Vs = dsm + VS_OFF;
    float* Bs = dsm + BS_OFF;

    const int tid = threadIdx.x, lane = tid & 31, wid = tid >> 5;
    const int warpM = wid & 3, warpN = wid >> 2;    // 4M x 2N
    const int g = lane >> 2, q4 = lane & 3;

    {   // stage A (rna(s)) pair-interleaved
        int r = tid >> 2, seg = tid & 3;
        int hh = seg >> 1, qq = seg & 1;
        const float* srcA = x + (size_t)(z0 + r) * 256 + hh * 32;
        float* dstA = As + r * 72 + hh * 36;
        #pragma unroll
        for (int t = 0; t < 2; ++t) {
            int je = qq * 4 + t * 2;
            float4 v0 = *(const float4*)(srcA + je * 4);
            float4 v1 = *(const float4*)(srcA + je * 4 + 4);
            *(float2*)(dstA + je * 4 + 0) = make_float2(u2f(rna(v0.x)), u2f(rna(v1.x)));
            *(float2*)(dstA + je * 4 + 2) = make_float2(u2f(rna(v0.y)), u2f(rna(v1.y)));
            *(float2*)(dstA + je * 4 + 4) = make_float2(u2f(rna(v0.z)), u2f(rna(v1.z)));
            *(float2*)(dstA + je * 4 + 6) = make_float2(u2f(rna(v0.w)), u2f(rna(v1.w)));
        }
    }
    {   // stage V vectorized
        int r = tid >> 2, vseg = tid & 3;
        const float4* srcV = (const float4*)(x + (size_t)(z0 + r) * 256 + 64);
        float4* dstV = (float4*)(Vs + r * 196);
        #pragma unroll
        for (int t = 0; t < 12; ++t)
            dstV[vseg * 12 + t] = srcV[vseg * 12 + t];
    }

    const int brow = tid >> 1, bhh = tid & 1;
    const float* bsrc0 = g_B3p + (size_t)brow * 64 + bhh * 32;
    float* bdst = Bs + brow * 72 + bhh * 36;

    float4 rg[8];
    #define LOAD_BT(IT) do {                                                      \
        const float* s = bsrc0 + (size_t)(IT) * 128 * 64;                         \
        _Pragma("unroll")                                                         \
        for (int t = 0; t < 8; ++t) rg[t] = *(const float4*)(s + t * 4);          \
    } while (0)
    #define STORE_BT() do {                                                       \
        _Pragma("unroll")                                                         \
        for (int t = 0; t < 4; ++t) {                                             \
            *(float2*)(bdst + t * 8 + 0) = make_float2(rg[2*t].x, rg[2*t+1].x);   \
            *(float2*)(bdst + t * 8 + 2) = make_float2(rg[2*t].y, rg[2*t+1].y);   \
            *(float2*)(bdst + t * 8 + 4) = make_float2(rg[2*t].z, rg[2*t+1].z);   \
            *(float2*)(bdst + t * 8 + 6) = make_float2(rg[2*t].w, rg[2*t+1].w);   \
        }                                                                         \
    } while (0)

    LOAD_BT(0);
    STORE_BT();
    __syncthreads();

    const float sc = 0.015625f;   // 1/64 == C3/sqrt(3)

    for (int it = 0; it < 32; ++it) {
        if (it + 1 < 32) LOAD_BT(it + 1);

        float acc[8][4];
        #pragma unroll
        for (int nt = 0; nt < 8; ++nt)
            #pragma unroll
            for (int j = 0; j < 4; ++j) acc[nt][j] = 0.0f;

        #pragma unroll
        for (int ch = 0; ch < 2; ++ch) {
            #pragma unroll
            for (int k8 = 0; k8 < 4; ++k8) {
                int ko = ch * 36 + k8 * 8 + q4 * 2;
                uint32_t a[4], b[8][2];
                {
                    float2 lo = *(const float2*)(As + (warpM * 16 + g) * 72 + ko);
                    float2 hi = *(const float2*)(As + (warpM * 16 + 8 + g) * 72 + ko);
                    a[0] = __float_as_uint(lo.x); a[1] = __float_as_uint(hi.x);
                    a[2] = __float_as_uint(lo.y); a[3] = __float_as_uint(hi.y);
                }
                #pragma unroll
                for (int nt = 0; nt < 8; ++nt) {
                    float2 bv = *(const float2*)(Bs + (warpN * 64 + nt * 8 + g) * 72 + ko);
                    b[nt][0] = __float_as_uint(bv.x); b[nt][1] = __float_as_uint(bv.y);
                }
                #pragma unroll
                for (int nt = 0; nt < 8; ++nt)
                    mma8(acc[nt], a, b[nt]);
            }
        }

        // epilogue: contract against v, reduce over q4 quad, store
        {
            int ra = warpM * 16 + g;
            int rb = ra + 8;
            float p[2][3] = {{0,0,0},{0,0,0}};
            #pragma unroll
            for (int nt = 0; nt < 8; ++nt) {
                int m0 = nt * 8 + q4 * 2;
                const float* va = Vs + ra * 196 + 3 * m0;
                const float* vb = Vs + rb * 196 + 3 * m0;
                float2 va01 = *(const float2*)(va);
                float2 va23 = *(const float2*)(va + 2);
                float2 va45 = *(const float2*)(va + 4);
                float2 vb01 = *(const float2*)(vb);
                float2 vb23 = *(const float2*)(vb + 2);
                float2 vb45 = *(const float2*)(vb + 4);
                float c0 = acc[nt][0], c1 = acc[nt][1];
                float d0 = acc[nt][2], d1 = acc[nt][3];
                p[0][0] += c0 * va01.x + c1 * va23.y;
                p[0][1] += c0 * va01.y + c1 * va45.x;
                p[0][2] += c0 * va23.x + c1 * va45.y;
                p[1][0] += d0 * vb01.x + d1 * vb23.y;
                p[1][1] += d0 * vb01.y + d1 * vb45.x;
                p[1][2] += d0 * vb23.x + d1 * vb45.y;
            }
            #pragma unroll
            for (int rr = 0; rr < 2; ++rr)
                #pragma unroll
                for (int k = 0; k < 3; ++k) {
                    p[rr][k] += __shfl_xor_sync(0xFFFFFFFF, p[rr][k], 1);
                    p[rr][k] += __shfl_xor_sync(0xFFFFFFFF, p[rr][k], 2);
                }
            if (q4 == 0) {
                int w = it * 2 + warpN;
                float* oa = out + (size_t)(z0 + ra) * NOUT + 64 + w * 3;
                float* ob = out + (size_t)(z0 + rb) * NOUT + 64 + w * 3;
                oa[0] = p[0][0] * sc; oa[1] = p[0][1] * sc; oa[2] = p[0][2] * sc;
                ob[0] = p[1][0] * sc; ob[1] = p[1][1] * sc; ob[2] = p[1][2] * sc;
            }
        }

        __syncthreads();                       // everyone done reading Bs
        if (it + 1 < 32) { STORE_BT(); __syncthreads(); }
    }
    #undef LOAD_BT
    #undef STORE_BT
}

// ===================== fused kernel: one grid for everything =====================
// bx 0..127      : out1   (z-tile bx)
// bx 128..511    : out2   (z-tile (bx-128)&127, comp (bx-128)>>7)
// bx 512..1023   : out0   (z-tile (bx-512)&127, K-split (bx-512)>>7)
__global__ __launch_bounds__(256) void fused_kernel(const float* __restrict__ x,
                                                    float* __restrict__ out) {
    extern __shared__ __align__(16) float dsm[];
    int bx = blockIdx.x;
    if (bx < 128) {
        tgemm_body(x, out, dsm, bx * 64);
    } else if (bx < 512) {
        int idx = bx - 128;
        main_body<2>(x, out, dsm, (idx & 127) * 64, idx >> 7);
    } else {
        int idx = bx - 512;
        main_body<0>(x, out, dsm, (idx & 127) * 64, idx >> 7);
    }
}

// ===================== launch =====================
extern "C" void kernel_launch(void* const* d_in, const int* in_sizes, int n_in,
                              void* d_out, int out_size) {
    const float* x  = (const float*)d_in[0];
    const float* w1 = (const float*)d_in[1];
    const float* w2 = (const float*)d_in[2];
    const float* w3 = (const float*)d_in[3];
    const float* w4 = (const float*)d_in[4];
    const float* w5 = (const float*)d_in[5];
    const float* w6 = (const float*)d_in[6];
    float* out = (float*)d_out;

    float c1  = (float)sqrt(1.0 / 4160.0);     // C1
    float c2  = (float)sqrt(1.0 / 12480.0);    // C2 == C4/sqrt(3)
    float c5s = (float)sqrt(1.0 / 62400.0);    // C5/sqrt(3)
    float c6s = (float)sqrt(1.0 / 4032.0);     // C6/sqrt(6)

    const int FUSED_SMEM = 27648 * 4 + NG0 * 2;   // 111,776 (covers all branches)
    cudaFuncSetAttribute(fused_kernel, cudaFuncAttributeMaxDynamicSharedMemorySize, FUSED_SMEM);

    cudaMemsetAsync(d_out, 0, (size_t)out_size * sizeof(float));
    init_tables_kernel<<<1, 64>>>();
    const int NTOT = 64 * K0TOT + 64 * K2TOT + 4096 * 64;
    prep_w_kernel<<<(NTOT + 255) / 256, 256>>>(w1, w2, w3, w4, w5, w6, c1, c2, c5s, c6s);

    fused_kernel<<<1024, 256, FUSED_SMEM>>>(x, out);
}